// round 1
// baseline (speedup 1.0000x reference)
#include <cuda_runtime.h>
#include <math.h>

#define Bb 32
#define Ss 24
#define Tt 24
#define Vv 30000
#define Ee 620
#define Hh 1000
#define Mm 500
#define RS (Ss*Bb)   /* 768 */
#define RT (Tt*Bb)   /* 768 */

// ---------------- scratch (device globals; no allocation allowed) ----------------
__device__ float g_Xsrc[RS*Ee];
__device__ float g_Ytgt[RT*Ee];
__device__ float g_Xr[RS*Hh];
__device__ float g_Xz[RS*Hh];
__device__ float g_Xc[RS*Hh];
__device__ float g_Yr[RT*Hh];
__device__ float g_Yz[RT*Hh];
__device__ float g_Yc[RT*Hh];
__device__ float g_Yo[RT*Hh];      // y @ V_o^T, 2M = 1000 cols
__device__ float g_hA[Bb*Hh];
__device__ float g_hB[Bb*Hh];
__device__ float g_rh[Bb*Hh];
__device__ float g_zb[Bb*Hh];
__device__ float g_cCr[Bb*Hh];
__device__ float g_cCz[Bb*Hh];
__device__ float g_cC [Bb*Hh];
__device__ float g_cCo[Bb*Hh];
__device__ float g_S[RT*Hh];       // decoder pre-update states, [T][B][H]
__device__ float g_tfull[RT*Hh];
__device__ float g_tmax[RT*Mm];

// ---------------- embedding gather: out[r= s*32+b][e] = emb[tok[b*L+s]][e] ----------------
__global__ void gather_emb(const int* __restrict__ tok, const float* __restrict__ emb,
                           float* __restrict__ out, int L)
{
    int r = blockIdx.x;
    int s = r >> 5, b = r & 31;
    int token = tok[b * L + s];
    const float* srcp = emb + (long)token * Ee;
    float* dst = out + (long)r * Ee;
    for (int e = threadIdx.x; e < Ee; e += blockDim.x) dst[e] = srcp[e];
}

// ---------------- generic tiled GEMM: C[m][n] = sum_k A[m][k]*B[n][k] (+epilogues) ----------------
// mode 0: C = acc (+bias[n])
// mode 1: C = tanh(acc (+bias[n]))
// mode 2: C = acc + add1[m*ldc+n] + add2[(m&31)*ldc+n]
// mode 3: logits write: m = t*32+b  ->  C[b*T*V + t*V + n] = acc
#define BM 64
#define BN 64
#define BK 16
__global__ void gemm_nt(const float* __restrict__ A, const float* __restrict__ Bm,
                        float* __restrict__ C,
                        int M, int N, int K, int lda, int ldb, int ldc,
                        const float* __restrict__ bias,
                        const float* __restrict__ add1,
                        const float* __restrict__ add2,
                        int mode)
{
    __shared__ float As[BK][BM + 4];
    __shared__ float Bs[BK][BN + 4];
    int t = threadIdx.x;
    int m0 = blockIdx.y * BM, n0 = blockIdx.x * BN;
    int tm = (t & 15) * 4, tn = (t >> 4) * 4;
    float acc[4][4] = {};

    for (int k0 = 0; k0 < K; k0 += BK) {
#pragma unroll
        for (int l = 0; l < 4; l++) {
            int e = t + l * 256;            // 0..1023
            int mm = e >> 4, kk = e & 15;
            int gm = m0 + mm, gk = k0 + kk;
            As[kk][mm] = (gm < M && gk < K) ? A[gm * lda + gk] : 0.f;
            int gn = n0 + mm;
            Bs[kk][mm] = (gn < N && gk < K) ? Bm[gn * ldb + gk] : 0.f;
        }
        __syncthreads();
#pragma unroll
        for (int kk = 0; kk < BK; kk++) {
            float4 a4 = *(const float4*)&As[kk][tm];
            float4 b4 = *(const float4*)&Bs[kk][tn];
            float av[4] = {a4.x, a4.y, a4.z, a4.w};
            float bv[4] = {b4.x, b4.y, b4.z, b4.w};
#pragma unroll
            for (int i = 0; i < 4; i++)
#pragma unroll
                for (int j = 0; j < 4; j++)
                    acc[i][j] += av[i] * bv[j];
        }
        __syncthreads();
    }

#pragma unroll
    for (int i = 0; i < 4; i++) {
        int gm = m0 + tm + i;
        if (gm >= M) continue;
#pragma unroll
        for (int j = 0; j < 4; j++) {
            int gn = n0 + tn + j;
            if (gn >= N) continue;
            float v = acc[i][j];
            if (mode == 0) {
                if (bias) v += bias[gn];
                C[gm * ldc + gn] = v;
            } else if (mode == 1) {
                if (bias) v += bias[gn];
                C[gm * ldc + gn] = tanhf(v);
            } else if (mode == 2) {
                v += add1[gm * ldc + gn] + add2[(gm & 31) * ldc + gn];
                C[gm * ldc + gn] = v;
            } else {
                int b = gm & 31, ti = gm >> 5;
                C[b * (Tt * Vv) + ti * Vv + gn] = v;
            }
        }
    }
}

// ---------------- recurrence step part 1: r and z gates ----------------
// grid: 126 blocks; blocks [0,63) -> r gate, [63,126) -> z gate; 16 cols per block.
// block = 128 threads (4 warps); lane = batch b; each warp computes 4 output cols.
__global__ void step_rz(const float* __restrict__ h,
                        const float* __restrict__ Ur, const float* __restrict__ Uz,
                        const float* __restrict__ Xr, const float* __restrict__ Xz,
                        const float* __restrict__ cR, const float* __restrict__ cZ,
                        float* __restrict__ rh, float* __restrict__ zout)
{
    __shared__ float hs[Bb * 68];
    __shared__ float us[16 * 68];
    int t = threadIdx.x;
    int lane = t & 31;
    int w = t >> 5;
    int gate = (blockIdx.x >= 63) ? 1 : 0;
    int jbase = (blockIdx.x - gate * 63) * 16;
    const float* U   = gate ? Uz : Ur;
    const float* X   = gate ? Xz : Xr;
    const float* ctx = gate ? cZ : cR;
    float acc[4] = {0.f, 0.f, 0.f, 0.f};

    for (int k0 = 0; k0 < Hh; k0 += 64) {
#pragma unroll
        for (int i = 0; i < 4; i++) {
            int f = t + i * 128;            // 0..511, covers 32 rows x 16 float4
            int b = f >> 4, kq = f & 15;
            int gk = k0 + kq * 4;
            float4 v;
            if (gk + 3 < Hh) v = *(const float4*)(h + b * Hh + gk);
            else {
                v.x = (gk     < Hh) ? h[b * Hh + gk    ] : 0.f;
                v.y = (gk + 1 < Hh) ? h[b * Hh + gk + 1] : 0.f;
                v.z = (gk + 2 < Hh) ? h[b * Hh + gk + 2] : 0.f;
                v.w = (gk + 3 < Hh) ? h[b * Hh + gk + 3] : 0.f;
            }
            *(float4*)(hs + b * 68 + kq * 4) = v;
        }
#pragma unroll
        for (int i = 0; i < 2; i++) {
            int f = t + i * 128;            // 0..255, covers 16 rows x 16 float4
            int j = f >> 4, kq = f & 15;
            int row = jbase + j;
            int gk = k0 + kq * 4;
            float4 v = {0.f, 0.f, 0.f, 0.f};
            if (row < Hh) {
                if (gk + 3 < Hh) v = *(const float4*)(U + row * Hh + gk);
                else {
                    if (gk     < Hh) v.x = U[row * Hh + gk    ];
                    if (gk + 1 < Hh) v.y = U[row * Hh + gk + 1];
                    if (gk + 2 < Hh) v.z = U[row * Hh + gk + 2];
                    if (gk + 3 < Hh) v.w = U[row * Hh + gk + 3];
                }
            }
            *(float4*)(us + j * 68 + kq * 4) = v;
        }
        __syncthreads();
#pragma unroll
        for (int k4 = 0; k4 < 16; k4++) {
            float4 hv = *(const float4*)(hs + lane * 68 + k4 * 4);
#pragma unroll
            for (int jj = 0; jj < 4; jj++) {
                float4 uv = *(const float4*)(us + (w * 4 + jj) * 68 + k4 * 4);
                acc[jj] += hv.x * uv.x + hv.y * uv.y + hv.z * uv.z + hv.w * uv.w;
            }
        }
        __syncthreads();
    }

#pragma unroll
    for (int jj = 0; jj < 4; jj++) {
        int j = jbase + w * 4 + jj;
        if (j < Hh) {
            int idx = lane * Hh + j;
            float pre = X[idx] + acc[jj];
            if (ctx) pre += ctx[idx];
            float sg = 1.f / (1.f + expf(-pre));
            if (gate == 0) rh[idx] = sg * h[idx];
            else           zout[idx] = sg;
        }
    }
}

// ---------------- recurrence step part 2: candidate + blend ----------------
// grid: 63 blocks x 16 cols.  hn = (1-z)*h + z*tanh(Xc + (r*h)@U^T (+ctx))
__global__ void step_cand(const float* __restrict__ h, const float* __restrict__ rhbuf,
                          const float* __restrict__ zbuf, const float* __restrict__ U,
                          const float* __restrict__ Xc, const float* __restrict__ ctx,
                          float* __restrict__ hn)
{
    __shared__ float hs[Bb * 68];
    __shared__ float us[16 * 68];
    int t = threadIdx.x;
    int lane = t & 31;
    int w = t >> 5;
    int jbase = blockIdx.x * 16;
    float acc[4] = {0.f, 0.f, 0.f, 0.f};

    for (int k0 = 0; k0 < Hh; k0 += 64) {
#pragma unroll
        for (int i = 0; i < 4; i++) {
            int f = t + i * 128;
            int b = f >> 4, kq = f & 15;
            int gk = k0 + kq * 4;
            float4 v;
            if (gk + 3 < Hh) v = *(const float4*)(rhbuf + b * Hh + gk);
            else {
                v.x = (gk     < Hh) ? rhbuf[b * Hh + gk    ] : 0.f;
                v.y = (gk + 1 < Hh) ? rhbuf[b * Hh + gk + 1] : 0.f;
                v.z = (gk + 2 < Hh) ? rhbuf[b * Hh + gk + 2] : 0.f;
                v.w = (gk + 3 < Hh) ? rhbuf[b * Hh + gk + 3] : 0.f;
            }
            *(float4*)(hs + b * 68 + kq * 4) = v;
        }
#pragma unroll
        for (int i = 0; i < 2; i++) {
            int f = t + i * 128;
            int j = f >> 4, kq = f & 15;
            int row = jbase + j;
            int gk = k0 + kq * 4;
            float4 v = {0.f, 0.f, 0.f, 0.f};
            if (row < Hh) {
                if (gk + 3 < Hh) v = *(const float4*)(U + row * Hh + gk);
                else {
                    if (gk     < Hh) v.x = U[row * Hh + gk    ];
                    if (gk + 1 < Hh) v.y = U[row * Hh + gk + 1];
                    if (gk + 2 < Hh) v.z = U[row * Hh + gk + 2];
                    if (gk + 3 < Hh) v.w = U[row * Hh + gk + 3];
                }
            }
            *(float4*)(us + j * 68 + kq * 4) = v;
        }
        __syncthreads();
#pragma unroll
        for (int k4 = 0; k4 < 16; k4++) {
            float4 hv = *(const float4*)(hs + lane * 68 + k4 * 4);
#pragma unroll
            for (int jj = 0; jj < 4; jj++) {
                float4 uv = *(const float4*)(us + (w * 4 + jj) * 68 + k4 * 4);
                acc[jj] += hv.x * uv.x + hv.y * uv.y + hv.z * uv.z + hv.w * uv.w;
            }
        }
        __syncthreads();
    }

#pragma unroll
    for (int jj = 0; jj < 4; jj++) {
        int j = jbase + w * 4 + jj;
        if (j < Hh) {
            int idx = lane * Hh + j;
            float pre = Xc[idx] + acc[jj];
            if (ctx) pre += ctx[idx];
            float cand = tanhf(pre);
            float zv = zbuf[idx];
            hn[idx] = (1.f - zv) * h[idx] + zv * cand;
        }
    }
}

// ---------------- maxout: tmax[r][m] = max(tfull[r][2m], tfull[r][2m+1]) ----------------
__global__ void maxout_k(const float* __restrict__ tf, float* __restrict__ tm)
{
    int i = blockIdx.x * blockDim.x + threadIdx.x;
    int total = RT * Mm;
    if (i < total) {
        int r = i / Mm, m = i - r * Mm;
        float a = tf[r * Hh + 2 * m];
        float b = tf[r * Hh + 2 * m + 1];
        tm[i] = fmaxf(a, b);
    }
}

// ---------------- host orchestration ----------------
extern "C" void kernel_launch(void* const* d_in, const int* in_sizes, int n_in,
                              void* d_out, int out_size)
{
    const int*   src     = (const int*)d_in[0];
    const int*   tgt     = (const int*)d_in[1];
    const float* src_emb = (const float*)d_in[3];
    const float* tgt_emb = (const float*)d_in[4];
    const float* enc_W   = (const float*)d_in[5];
    const float* enc_Wz  = (const float*)d_in[6];
    const float* enc_Wr  = (const float*)d_in[7];
    const float* enc_U   = (const float*)d_in[8];
    const float* enc_Uz  = (const float*)d_in[9];
    const float* enc_Ur  = (const float*)d_in[10];
    const float* enc_b   = (const float*)d_in[11];
    const float* enc_bz  = (const float*)d_in[12];
    const float* enc_br  = (const float*)d_in[13];
    const float* dec_W   = (const float*)d_in[14];
    const float* dec_Wz  = (const float*)d_in[15];
    const float* dec_Wr  = (const float*)d_in[16];
    const float* dec_U   = (const float*)d_in[17];
    const float* dec_Uz  = (const float*)d_in[18];
    const float* dec_Ur  = (const float*)d_in[19];
    const float* dec_C   = (const float*)d_in[20];
    const float* dec_Cz  = (const float*)d_in[21];
    const float* dec_Cr  = (const float*)d_in[22];
    const float* dec_b   = (const float*)d_in[23];
    const float* dec_bz  = (const float*)d_in[24];
    const float* dec_br  = (const float*)d_in[25];
    const float* W_s     = (const float*)d_in[26];
    const float* U_o     = (const float*)d_in[27];
    const float* V_o     = (const float*)d_in[28];
    const float* C_o     = (const float*)d_in[29];
    const float* W_o     = (const float*)d_in[30];
    float* out = (float*)d_out;

    float *Xsrc, *Ytgt, *Xr, *Xz, *Xc, *Yr, *Yz, *Yc, *Yo;
    float *hA, *hB, *rh, *zb, *cCr, *cCz, *cC, *cCo, *Sst, *tfull, *tmax;
    cudaGetSymbolAddress((void**)&Xsrc, g_Xsrc);
    cudaGetSymbolAddress((void**)&Ytgt, g_Ytgt);
    cudaGetSymbolAddress((void**)&Xr, g_Xr);
    cudaGetSymbolAddress((void**)&Xz, g_Xz);
    cudaGetSymbolAddress((void**)&Xc, g_Xc);
    cudaGetSymbolAddress((void**)&Yr, g_Yr);
    cudaGetSymbolAddress((void**)&Yz, g_Yz);
    cudaGetSymbolAddress((void**)&Yc, g_Yc);
    cudaGetSymbolAddress((void**)&Yo, g_Yo);
    cudaGetSymbolAddress((void**)&hA, g_hA);
    cudaGetSymbolAddress((void**)&hB, g_hB);
    cudaGetSymbolAddress((void**)&rh, g_rh);
    cudaGetSymbolAddress((void**)&zb, g_zb);
    cudaGetSymbolAddress((void**)&cCr, g_cCr);
    cudaGetSymbolAddress((void**)&cCz, g_cCz);
    cudaGetSymbolAddress((void**)&cC,  g_cC);
    cudaGetSymbolAddress((void**)&cCo, g_cCo);
    cudaGetSymbolAddress((void**)&Sst, g_S);
    cudaGetSymbolAddress((void**)&tfull, g_tfull);
    cudaGetSymbolAddress((void**)&tmax, g_tmax);

    const size_t stateBytes = (size_t)Bb * Hh * sizeof(float);

    // ---- phase 0: gathers + input projections (biases folded) ----
    gather_emb<<<RS, 128>>>(src, src_emb, Xsrc, Ss);
    gather_emb<<<RT, 128>>>(tgt, tgt_emb, Ytgt, Tt);

    dim3 gP0((Hh + BN - 1) / BN, (RS + BM - 1) / BM);   // (16, 12)
    gemm_nt<<<gP0, 256>>>(Xsrc, enc_Wr, Xr, RS, Hh, Ee, Ee, Ee, Hh, enc_br, nullptr, nullptr, 0);
    gemm_nt<<<gP0, 256>>>(Xsrc, enc_Wz, Xz, RS, Hh, Ee, Ee, Ee, Hh, enc_bz, nullptr, nullptr, 0);
    gemm_nt<<<gP0, 256>>>(Xsrc, enc_W,  Xc, RS, Hh, Ee, Ee, Ee, Hh, enc_b,  nullptr, nullptr, 0);
    gemm_nt<<<gP0, 256>>>(Ytgt, dec_Wr, Yr, RT, Hh, Ee, Ee, Ee, Hh, dec_br, nullptr, nullptr, 0);
    gemm_nt<<<gP0, 256>>>(Ytgt, dec_Wz, Yz, RT, Hh, Ee, Ee, Ee, Hh, dec_bz, nullptr, nullptr, 0);
    gemm_nt<<<gP0, 256>>>(Ytgt, dec_W,  Yc, RT, Hh, Ee, Ee, Ee, Hh, dec_b,  nullptr, nullptr, 0);
    gemm_nt<<<gP0, 256>>>(Ytgt, V_o,    Yo, RT, Hh, Ee, Ee, Ee, Hh, nullptr, nullptr, nullptr, 0);

    // ---- phase 1: encoder recurrence ----
    cudaMemsetAsync(hA, 0, stateBytes);
    float* cur = hA;
    float* nxt = hB;
    for (int t = 0; t < Ss; t++) {
        const float* Xr_t = Xr + (size_t)t * Bb * Hh;
        const float* Xz_t = Xz + (size_t)t * Bb * Hh;
        const float* Xc_t = Xc + (size_t)t * Bb * Hh;
        step_rz<<<126, 128>>>(cur, enc_Ur, enc_Uz, Xr_t, Xz_t, nullptr, nullptr, rh, zb);
        step_cand<<<63, 128>>>(cur, rh, zb, enc_U, Xc_t, nullptr, nxt);
        float* tmp = cur; cur = nxt; nxt = tmp;
    }
    float* c = cur;          // final encoder state
    float* s0 = nxt;         // free buffer

    // ---- phase 2: s0 and fixed context projections ----
    dim3 gCtx((Hh + BN - 1) / BN, 1);
    gemm_nt<<<gCtx, 256>>>(c, W_s,    s0,  Bb, Hh, Hh, Hh, Hh, Hh, nullptr, nullptr, nullptr, 1);
    gemm_nt<<<gCtx, 256>>>(c, dec_Cr, cCr, Bb, Hh, Hh, Hh, Hh, Hh, nullptr, nullptr, nullptr, 0);
    gemm_nt<<<gCtx, 256>>>(c, dec_Cz, cCz, Bb, Hh, Hh, Hh, Hh, Hh, nullptr, nullptr, nullptr, 0);
    gemm_nt<<<gCtx, 256>>>(c, dec_C,  cC,  Bb, Hh, Hh, Hh, Hh, Hh, nullptr, nullptr, nullptr, 0);
    gemm_nt<<<gCtx, 256>>>(c, C_o,    cCo, Bb, Hh, Hh, Hh, Hh, Hh, nullptr, nullptr, nullptr, 0);

    // ---- phase 3: decoder recurrence (store pre-update states) ----
    cur = s0;
    nxt = c;                 // c no longer needed
    for (int t = 0; t < Tt; t++) {
        cudaMemcpyAsync(Sst + (size_t)t * Bb * Hh, cur, stateBytes, cudaMemcpyDeviceToDevice);
        const float* Yr_t = Yr + (size_t)t * Bb * Hh;
        const float* Yz_t = Yz + (size_t)t * Bb * Hh;
        const float* Yc_t = Yc + (size_t)t * Bb * Hh;
        step_rz<<<126, 128>>>(cur, dec_Ur, dec_Uz, Yr_t, Yz_t, cCr, cCz, rh, zb);
        step_cand<<<63, 128>>>(cur, rh, zb, dec_U, Yc_t, cC, nxt);
        float* tmp = cur; cur = nxt; nxt = tmp;
    }

    // ---- phase 4: batched output layer ----
    dim3 gTf((Hh + BN - 1) / BN, (RT + BM - 1) / BM);
    gemm_nt<<<gTf, 256>>>(Sst, U_o, tfull, RT, Hh, Hh, Hh, Hh, Hh, nullptr, Yo, cCo, 2);

    int totMax = RT * Mm;
    maxout_k<<<(totMax + 255) / 256, 256>>>(tfull, tmax);

    dim3 gLg((Vv + BN - 1) / BN, (RT + BM - 1) / BM);   // (469, 12)
    gemm_nt<<<gLg, 256>>>(tmax, W_o, out, RT, Vv, Mm, Mm, Mm, Vv, nullptr, nullptr, nullptr, 3);
}

// round 2
// speedup vs baseline: 1.8684x; 1.8684x over previous
#include <cuda_runtime.h>
#include <cuda_bf16.h>
#include <math.h>
#include <stdint.h>

#define Bb 32
#define Ss 24
#define Tt 24
#define Vv 30000
#define Ee 620
#define Hh 1000
#define Mm 500
#define RS (Ss*Bb)   /* 768 */
#define RT (Tt*Bb)   /* 768 */

// ---------------- scratch (device globals) ----------------
__device__ float g_Xsrc[RS*Ee];
__device__ float g_Ytgt[RT*Ee];
__device__ float g_Xr[RS*Hh];
__device__ float g_Xz[RS*Hh];
__device__ float g_Xc[RS*Hh];
__device__ float g_Yr[RT*Hh];
__device__ float g_Yz[RT*Hh];
__device__ float g_Yc[RT*Hh];
__device__ float g_Yo[RT*Hh];
__device__ float g_hA[Bb*Hh];
__device__ float g_hB[Bb*Hh];
__device__ float g_rh[Bb*Hh];
__device__ float g_zb[Bb*Hh];
__device__ float g_cCr[Bb*Hh];
__device__ float g_cCz[Bb*Hh];
__device__ float g_cC [Bb*Hh];
__device__ float g_cCo[Bb*Hh];
__device__ float g_S[RT*Hh];
__device__ float g_tfull[RT*Hh];
__device__ float g_tmax[RT*Mm];

// ---------------- embedding gather ----------------
__global__ void gather_emb(const int* __restrict__ tok, const float* __restrict__ emb,
                           float* __restrict__ out, int L)
{
    int r = blockIdx.x;
    int s = r >> 5, b = r & 31;
    int token = tok[b * L + s];
    const float* srcp = emb + (long)token * Ee;
    float* dst = out + (long)r * Ee;
    for (int e = threadIdx.x; e < Ee; e += blockDim.x) dst[e] = srcp[e];
}

// ================= tensor-core bf16x3 GEMM =================
// C[m][n] = sum_k A[m][k] * B[n][k], A,B fp32; split each into hi+lo bf16,
// accumulate AhiBhi + AhiBlo + AloBhi in fp32 (error ~1e-5 rel).
// modes: 0: +bias[n]; 1: tanh(+bias); 2: +add1[m*ldc+n]+add2[(m&31)*ldc+n];
//        3: logits scatter  C[(m&31)*T*V + (m>>5)*V + n]
#define TBM 128
#define TBN 128
#define TBK 16
#define SKS 24   // smem row stride (bf16 elems): 48B, conflict-free for ldmatrix

__device__ __forceinline__ uint32_t smem_u32(const void* p) {
    return (uint32_t)__cvta_generic_to_shared(p);
}
__device__ __forceinline__ void ldsm4(uint32_t &r0, uint32_t &r1, uint32_t &r2, uint32_t &r3, uint32_t a) {
    asm volatile("ldmatrix.sync.aligned.m8n8.x4.shared.b16 {%0,%1,%2,%3}, [%4];\n"
        : "=r"(r0), "=r"(r1), "=r"(r2), "=r"(r3) : "r"(a));
}
__device__ __forceinline__ void mma_bf16(float* c, const uint32_t* a, uint32_t b0, uint32_t b1) {
    asm volatile("mma.sync.aligned.m16n8k16.row.col.f32.bf16.bf16.f32 "
        "{%0,%1,%2,%3},{%4,%5,%6,%7},{%8,%9},{%0,%1,%2,%3};\n"
        : "+f"(c[0]), "+f"(c[1]), "+f"(c[2]), "+f"(c[3])
        : "r"(a[0]), "r"(a[1]), "r"(a[2]), "r"(a[3]), "r"(b0), "r"(b1));
}

__global__ __launch_bounds__(256, 2)
void mma_gemm(const float* __restrict__ A, const float* __restrict__ Bm, float* __restrict__ C,
              int M, int N, int K, int lda, int ldb, int ldc,
              const float* __restrict__ bias,
              const float* __restrict__ add1, const float* __restrict__ add2, int mode)
{
    __shared__ __align__(16) __nv_bfloat16 Ah[TBM*SKS];
    __shared__ __align__(16) __nv_bfloat16 Al[TBM*SKS];
    __shared__ __align__(16) __nv_bfloat16 Bh[TBN*SKS];
    __shared__ __align__(16) __nv_bfloat16 Bl[TBN*SKS];

    int t = threadIdx.x, lane = t & 31, wid = t >> 5;
    int wm = wid & 1, wn = wid >> 1;                 // warp tile 64(m) x 32(n)
    int m0 = blockIdx.y * TBM, n0 = blockIdx.x * TBN;

    float acc[4][4][4];
#pragma unroll
    for (int i = 0; i < 4; i++)
#pragma unroll
        for (int j = 0; j < 4; j++)
#pragma unroll
            for (int c = 0; c < 4; c++) acc[i][j][c] = 0.f;

    // frag address offsets (lane-dependent)
    int sel = lane >> 3, l7 = lane & 7;
    int ar = (sel & 1) * 8 + l7;     // A: row-in-16
    int ac = (sel >> 1) * 8;         // A: k offset
    int br = (sel >> 1) * 8 + l7;    // B: n-in-16
    int bc = (sel & 1) * 8;          // B: k offset

    int KT = (K + TBK - 1) / TBK;
    float4 pa[2], pb[2];

    // per-thread tile-load mapping: idx = t + i*256 -> row = idx>>2, k4 = idx&3
    auto loadT = [&](const float* P, int mN, int ld, int base0, int kt, float4 v[2]) {
#pragma unroll
        for (int i = 0; i < 2; i++) {
            int idx = t + i * 256;
            int row = idx >> 2, k4 = idx & 3;
            int gr = base0 + row, gk = kt * TBK + k4 * 4;
            float4 x = {0.f, 0.f, 0.f, 0.f};
            if (gr < mN && gk < K)                 // K always mult of 4 here
                x = *(const float4*)(P + (size_t)gr * ld + gk);
            v[i] = x;
        }
    };
    auto storeT = [&](__nv_bfloat16* Sh, __nv_bfloat16* Sl, const float4 v[2]) {
#pragma unroll
        for (int i = 0; i < 2; i++) {
            int idx = t + i * 256;
            int row = idx >> 2, k4 = idx & 3;
            const float* f = (const float*)&v[i];
#pragma unroll
            for (int c = 0; c < 4; c++) {
                float x = f[c];
                __nv_bfloat16 h = __float2bfloat16(x);
                __nv_bfloat16 l = __float2bfloat16(x - __bfloat162float(h));
                Sh[row * SKS + k4 * 4 + c] = h;
                Sl[row * SKS + k4 * 4 + c] = l;
            }
        }
    };

    loadT(A, M, lda, m0, 0, pa);
    loadT(Bm, N, ldb, n0, 0, pb);

    for (int kt = 0; kt < KT; kt++) {
        __syncthreads();
        storeT(Ah, Al, pa);
        storeT(Bh, Bl, pb);
        __syncthreads();
        if (kt + 1 < KT) {
            loadT(A, M, lda, m0, kt + 1, pa);
            loadT(Bm, N, ldb, n0, kt + 1, pb);
        }
        // fragments
        uint32_t af[4][4], bh[4][2], bl[4][2];
#pragma unroll
        for (int mi = 0; mi < 4; mi++) {
            uint32_t addr = smem_u32(&Ah[(wm * 64 + mi * 16 + ar) * SKS + ac]);
            ldsm4(af[mi][0], af[mi][1], af[mi][2], af[mi][3], addr);
        }
#pragma unroll
        for (int p = 0; p < 2; p++) {
            uint32_t addr = smem_u32(&Bh[(wn * 32 + p * 16 + br) * SKS + bc]);
            uint32_t r0, r1, r2, r3;
            ldsm4(r0, r1, r2, r3, addr);
            bh[2*p][0] = r0; bh[2*p][1] = r1; bh[2*p+1][0] = r2; bh[2*p+1][1] = r3;
            addr = smem_u32(&Bl[(wn * 32 + p * 16 + br) * SKS + bc]);
            ldsm4(r0, r1, r2, r3, addr);
            bl[2*p][0] = r0; bl[2*p][1] = r1; bl[2*p+1][0] = r2; bl[2*p+1][1] = r3;
        }
#pragma unroll
        for (int mi = 0; mi < 4; mi++)
#pragma unroll
            for (int ni = 0; ni < 4; ni++) {
                mma_bf16(acc[mi][ni], af[mi], bh[ni][0], bh[ni][1]);
                mma_bf16(acc[mi][ni], af[mi], bl[ni][0], bl[ni][1]);
            }
        // overwrite A-frags with lo part
#pragma unroll
        for (int mi = 0; mi < 4; mi++) {
            uint32_t addr = smem_u32(&Al[(wm * 64 + mi * 16 + ar) * SKS + ac]);
            ldsm4(af[mi][0], af[mi][1], af[mi][2], af[mi][3], addr);
        }
#pragma unroll
        for (int mi = 0; mi < 4; mi++)
#pragma unroll
            for (int ni = 0; ni < 4; ni++)
                mma_bf16(acc[mi][ni], af[mi], bh[ni][0], bh[ni][1]);
    }

    // epilogue
    int g = lane >> 2, tig = lane & 3;
#pragma unroll
    for (int mi = 0; mi < 4; mi++) {
#pragma unroll
        for (int ni = 0; ni < 4; ni++) {
#pragma unroll
            for (int c = 0; c < 4; c++) {
                int row = m0 + wm * 64 + mi * 16 + g + ((c >> 1) ? 8 : 0);
                int col = n0 + wn * 32 + ni * 8 + tig * 2 + (c & 1);
                if (row >= M || col >= N) continue;
                float v = acc[mi][ni][c];
                if (mode == 0) {
                    if (bias) v += bias[col];
                    C[(size_t)row * ldc + col] = v;
                } else if (mode == 1) {
                    if (bias) v += bias[col];
                    C[(size_t)row * ldc + col] = tanhf(v);
                } else if (mode == 2) {
                    v += add1[(size_t)row * ldc + col] + add2[(size_t)(row & 31) * ldc + col];
                    C[(size_t)row * ldc + col] = v;
                } else {
                    int b = row & 31, ti = row >> 5;
                    C[(size_t)b * (Tt * Vv) + (size_t)ti * Vv + col] = v;
                }
            }
        }
    }
}

// ================= recurrence kernels (fp32, 8 warps, warp-per-col) =================
// step_rz: grid 250 blocks (125 r, 125 z), 8 cols/block, warp w -> col jbase+w
__global__ __launch_bounds__(256, 4)
void step_rz(const float* __restrict__ h,
             const float* __restrict__ Ur, const float* __restrict__ Uz,
             const float* __restrict__ Xr, const float* __restrict__ Xz,
             const float* __restrict__ cR, const float* __restrict__ cZ,
             float* __restrict__ rh, float* __restrict__ zout)
{
    __shared__ float hs[32 * 68];
    __shared__ float us[8 * 68];
    int t = threadIdx.x, lane = t & 31, w = t >> 5;
    int gate = (blockIdx.x >= 125) ? 1 : 0;
    int jbase = (blockIdx.x - gate * 125) * 8;
    const float* U   = gate ? Uz : Ur;
    const float* X   = gate ? Xz : Xr;
    const float* ctx = gate ? cZ : cR;
    float a0 = 0.f, a1 = 0.f;

    for (int k0 = 0; k0 < Hh; k0 += 64) {
#pragma unroll
        for (int i = 0; i < 2; i++) {
            int f = t + i * 256;
            int b = f >> 4, kq = f & 15;
            int gk = k0 + kq * 4;
            float4 v = {0.f, 0.f, 0.f, 0.f};
            if (gk < Hh) v = *(const float4*)(h + b * Hh + gk);
            *(float4*)(hs + b * 68 + kq * 4) = v;
        }
        if (t < 128) {
            int j = t >> 4, kq = t & 15;
            int gk = k0 + kq * 4;
            float4 v = {0.f, 0.f, 0.f, 0.f};
            if (gk < Hh) v = *(const float4*)(U + (jbase + j) * Hh + gk);
            *(float4*)(us + j * 68 + kq * 4) = v;
        }
        __syncthreads();
#pragma unroll
        for (int k4 = 0; k4 < 16; k4++) {
            float4 hv = *(const float4*)(hs + lane * 68 + k4 * 4);
            float4 uv = *(const float4*)(us + w * 68 + k4 * 4);
            float d = hv.x * uv.x + hv.y * uv.y + hv.z * uv.z + hv.w * uv.w;
            if (k4 & 1) a1 += d; else a0 += d;
        }
        __syncthreads();
    }

    int j = jbase + w;
    int idx = lane * Hh + j;
    float pre = X[idx] + a0 + a1;
    if (ctx) pre += ctx[idx];
    float sg = 1.f / (1.f + expf(-pre));
    if (gate == 0) rh[idx] = sg * h[idx];
    else           zout[idx] = sg;
}

// step_cand: grid 125 blocks.  hn = (1-z)*h + z*tanh(Xc + (r*h)@U^T (+ctx))
__global__ __launch_bounds__(256, 4)
void step_cand(const float* __restrict__ h, const float* __restrict__ rhbuf,
               const float* __restrict__ zbuf, const float* __restrict__ U,
               const float* __restrict__ Xc, const float* __restrict__ ctx,
               float* __restrict__ hn)
{
    __shared__ float hs[32 * 68];
    __shared__ float us[8 * 68];
    int t = threadIdx.x, lane = t & 31, w = t >> 5;
    int jbase = blockIdx.x * 8;
    float a0 = 0.f, a1 = 0.f;

    for (int k0 = 0; k0 < Hh; k0 += 64) {
#pragma unroll
        for (int i = 0; i < 2; i++) {
            int f = t + i * 256;
            int b = f >> 4, kq = f & 15;
            int gk = k0 + kq * 4;
            float4 v = {0.f, 0.f, 0.f, 0.f};
            if (gk < Hh) v = *(const float4*)(rhbuf + b * Hh + gk);
            *(float4*)(hs + b * 68 + kq * 4) = v;
        }
        if (t < 128) {
            int j = t >> 4, kq = t & 15;
            int gk = k0 + kq * 4;
            float4 v = {0.f, 0.f, 0.f, 0.f};
            if (gk < Hh) v = *(const float4*)(U + (jbase + j) * Hh + gk);
            *(float4*)(us + j * 68 + kq * 4) = v;
        }
        __syncthreads();
#pragma unroll
        for (int k4 = 0; k4 < 16; k4++) {
            float4 hv = *(const float4*)(hs + lane * 68 + k4 * 4);
            float4 uv = *(const float4*)(us + w * 68 + k4 * 4);
            float d = hv.x * uv.x + hv.y * uv.y + hv.z * uv.z + hv.w * uv.w;
            if (k4 & 1) a1 += d; else a0 += d;
        }
        __syncthreads();
    }

    int j = jbase + w;
    int idx = lane * Hh + j;
    float pre = Xc[idx] + a0 + a1;
    if (ctx) pre += ctx[idx];
    float cand = tanhf(pre);
    float zv = zbuf[idx];
    hn[idx] = (1.f - zv) * h[idx] + zv * cand;
}

// ---------------- maxout ----------------
__global__ void maxout_k(const float* __restrict__ tf, float* __restrict__ tm)
{
    int i = blockIdx.x * blockDim.x + threadIdx.x;
    int total = RT * Mm;
    if (i < total) {
        int r = i / Mm, m = i - r * Mm;
        float a = tf[r * Hh + 2 * m];
        float b = tf[r * Hh + 2 * m + 1];
        tm[i] = fmaxf(a, b);
    }
}

// ---------------- host orchestration ----------------
extern "C" void kernel_launch(void* const* d_in, const int* in_sizes, int n_in,
                              void* d_out, int out_size)
{
    const int*   src     = (const int*)d_in[0];
    const int*   tgt     = (const int*)d_in[1];
    const float* src_emb = (const float*)d_in[3];
    const float* tgt_emb = (const float*)d_in[4];
    const float* enc_W   = (const float*)d_in[5];
    const float* enc_Wz  = (const float*)d_in[6];
    const float* enc_Wr  = (const float*)d_in[7];
    const float* enc_U   = (const float*)d_in[8];
    const float* enc_Uz  = (const float*)d_in[9];
    const float* enc_Ur  = (const float*)d_in[10];
    const float* enc_b   = (const float*)d_in[11];
    const float* enc_bz  = (const float*)d_in[12];
    const float* enc_br  = (const float*)d_in[13];
    const float* dec_W   = (const float*)d_in[14];
    const float* dec_Wz  = (const float*)d_in[15];
    const float* dec_Wr  = (const float*)d_in[16];
    const float* dec_U   = (const float*)d_in[17];
    const float* dec_Uz  = (const float*)d_in[18];
    const float* dec_Ur  = (const float*)d_in[19];
    const float* dec_C   = (const float*)d_in[20];
    const float* dec_Cz  = (const float*)d_in[21];
    const float* dec_Cr  = (const float*)d_in[22];
    const float* dec_b   = (const float*)d_in[23];
    const float* dec_bz  = (const float*)d_in[24];
    const float* dec_br  = (const float*)d_in[25];
    const float* W_s     = (const float*)d_in[26];
    const float* U_o     = (const float*)d_in[27];
    const float* V_o     = (const float*)d_in[28];
    const float* C_o     = (const float*)d_in[29];
    const float* W_o     = (const float*)d_in[30];
    float* out = (float*)d_out;

    float *Xsrc, *Ytgt, *Xr, *Xz, *Xc, *Yr, *Yz, *Yc, *Yo;
    float *hA, *hB, *rh, *zb, *cCr, *cCz, *cC, *cCo, *Sst, *tfull, *tmax;
    cudaGetSymbolAddress((void**)&Xsrc, g_Xsrc);
    cudaGetSymbolAddress((void**)&Ytgt, g_Ytgt);
    cudaGetSymbolAddress((void**)&Xr, g_Xr);
    cudaGetSymbolAddress((void**)&Xz, g_Xz);
    cudaGetSymbolAddress((void**)&Xc, g_Xc);
    cudaGetSymbolAddress((void**)&Yr, g_Yr);
    cudaGetSymbolAddress((void**)&Yz, g_Yz);
    cudaGetSymbolAddress((void**)&Yc, g_Yc);
    cudaGetSymbolAddress((void**)&Yo, g_Yo);
    cudaGetSymbolAddress((void**)&hA, g_hA);
    cudaGetSymbolAddress((void**)&hB, g_hB);
    cudaGetSymbolAddress((void**)&rh, g_rh);
    cudaGetSymbolAddress((void**)&zb, g_zb);
    cudaGetSymbolAddress((void**)&cCr, g_cCr);
    cudaGetSymbolAddress((void**)&cCz, g_cCz);
    cudaGetSymbolAddress((void**)&cC,  g_cC);
    cudaGetSymbolAddress((void**)&cCo, g_cCo);
    cudaGetSymbolAddress((void**)&Sst, g_S);
    cudaGetSymbolAddress((void**)&tfull, g_tfull);
    cudaGetSymbolAddress((void**)&tmax, g_tmax);

    const size_t stateBytes = (size_t)Bb * Hh * sizeof(float);

    // ---- phase 0: gathers + input projections ----
    gather_emb<<<RS, 128>>>(src, src_emb, Xsrc, Ss);
    gather_emb<<<RT, 128>>>(tgt, tgt_emb, Ytgt, Tt);

    dim3 gP0((Hh + TBN - 1) / TBN, (RS + TBM - 1) / TBM);   // (8, 6)
    mma_gemm<<<gP0, 256>>>(Xsrc, enc_Wr, Xr, RS, Hh, Ee, Ee, Ee, Hh, enc_br, nullptr, nullptr, 0);
    mma_gemm<<<gP0, 256>>>(Xsrc, enc_Wz, Xz, RS, Hh, Ee, Ee, Ee, Hh, enc_bz, nullptr, nullptr, 0);
    mma_gemm<<<gP0, 256>>>(Xsrc, enc_W,  Xc, RS, Hh, Ee, Ee, Ee, Hh, enc_b,  nullptr, nullptr, 0);
    mma_gemm<<<gP0, 256>>>(Ytgt, dec_Wr, Yr, RT, Hh, Ee, Ee, Ee, Hh, dec_br, nullptr, nullptr, 0);
    mma_gemm<<<gP0, 256>>>(Ytgt, dec_Wz, Yz, RT, Hh, Ee, Ee, Ee, Hh, dec_bz, nullptr, nullptr, 0);
    mma_gemm<<<gP0, 256>>>(Ytgt, dec_W,  Yc, RT, Hh, Ee, Ee, Ee, Hh, dec_b,  nullptr, nullptr, 0);
    mma_gemm<<<gP0, 256>>>(Ytgt, V_o,    Yo, RT, Hh, Ee, Ee, Ee, Hh, nullptr, nullptr, nullptr, 0);

    // ---- phase 1: encoder recurrence ----
    cudaMemsetAsync(hA, 0, stateBytes);
    float* cur = hA;
    float* nxt = hB;
    for (int t = 0; t < Ss; t++) {
        const float* Xr_t = Xr + (size_t)t * Bb * Hh;
        const float* Xz_t = Xz + (size_t)t * Bb * Hh;
        const float* Xc_t = Xc + (size_t)t * Bb * Hh;
        step_rz<<<250, 256>>>(cur, enc_Ur, enc_Uz, Xr_t, Xz_t, nullptr, nullptr, rh, zb);
        step_cand<<<125, 256>>>(cur, rh, zb, enc_U, Xc_t, nullptr, nxt);
        float* tmp = cur; cur = nxt; nxt = tmp;
    }
    float* c = cur;
    float* s0 = nxt;

    // ---- phase 2: s0 and fixed context projections ----
    dim3 gCtx((Hh + TBN - 1) / TBN, 1);
    mma_gemm<<<gCtx, 256>>>(c, W_s,    s0,  Bb, Hh, Hh, Hh, Hh, Hh, nullptr, nullptr, nullptr, 1);
    mma_gemm<<<gCtx, 256>>>(c, dec_Cr, cCr, Bb, Hh, Hh, Hh, Hh, Hh, nullptr, nullptr, nullptr, 0);
    mma_gemm<<<gCtx, 256>>>(c, dec_Cz, cCz, Bb, Hh, Hh, Hh, Hh, Hh, nullptr, nullptr, nullptr, 0);
    mma_gemm<<<gCtx, 256>>>(c, dec_C,  cC,  Bb, Hh, Hh, Hh, Hh, Hh, nullptr, nullptr, nullptr, 0);
    mma_gemm<<<gCtx, 256>>>(c, C_o,    cCo, Bb, Hh, Hh, Hh, Hh, Hh, nullptr, nullptr, nullptr, 0);

    // ---- phase 3: decoder recurrence (store pre-update states) ----
    cur = s0;
    nxt = c;
    for (int t = 0; t < Tt; t++) {
        cudaMemcpyAsync(Sst + (size_t)t * Bb * Hh, cur, stateBytes, cudaMemcpyDeviceToDevice);
        const float* Yr_t = Yr + (size_t)t * Bb * Hh;
        const float* Yz_t = Yz + (size_t)t * Bb * Hh;
        const float* Yc_t = Yc + (size_t)t * Bb * Hh;
        step_rz<<<250, 256>>>(cur, dec_Ur, dec_Uz, Yr_t, Yz_t, cCr, cCz, rh, zb);
        step_cand<<<125, 256>>>(cur, rh, zb, dec_U, Yc_t, cC, nxt);
        float* tmp = cur; cur = nxt; nxt = tmp;
    }

    // ---- phase 4: batched output layer ----
    dim3 gTf((Hh + TBN - 1) / TBN, (RT + TBM - 1) / TBM);   // (8, 6)
    mma_gemm<<<gTf, 256>>>(Sst, U_o, tfull, RT, Hh, Hh, Hh, Hh, Hh, nullptr, Yo, cCo, 2);

    int totMax = RT * Mm;
    maxout_k<<<(totMax + 255) / 256, 256>>>(tfull, tmax);

    dim3 gLg((Vv + TBN - 1) / TBN, (RT + TBM - 1) / TBM);   // (235, 6)
    mma_gemm<<<gLg, 256>>>(tmax, W_o, out, RT, Vv, Mm, Mm, Mm, Vv, nullptr, nullptr, nullptr, 3);
}

// round 3
// speedup vs baseline: 3.1010x; 1.6597x over previous
#include <cuda_runtime.h>
#include <cuda_bf16.h>
#include <math.h>
#include <stdint.h>

#define Bb 32
#define Ss 24
#define Tt 24
#define Vv 30000
#define Ee 620
#define Hh 1000
#define Mm 500
#define RS (Ss*Bb)   /* 768 */
#define RT (Tt*Bb)   /* 768 */
#define NBLK 125
#define NCOLS 8

// ---------------- scratch (device globals) ----------------
__device__ float g_Xsrc[RS*Ee];
__device__ float g_Ytgt[RT*Ee];
__device__ float g_Xr[RS*Hh];    // [t][j][b]
__device__ float g_Xz[RS*Hh];
__device__ float g_Xc[RS*Hh];
__device__ float g_Yr[RT*Hh];
__device__ float g_Yz[RT*Hh];
__device__ float g_Yc[RT*Hh];
__device__ float g_Yo[RT*Hh];    // normal [row][2M]
__device__ float g_hT2[Hh*Bb];   // paired transposed state (encoder)
__device__ float g_s0T[Hh*Bb];   // paired transposed state (decoder)
__device__ float g_rhT2[Hh*Bb];
__device__ float g_cCrT[Hh*Bb];  // [j][b]
__device__ float g_cCzT[Hh*Bb];
__device__ float g_cCT [Hh*Bb];
__device__ float g_cCo[Bb*Hh];   // normal [b][2M]
__device__ float g_S[RT*Hh];     // pre-update decoder states, normal [t*32+b][H]
__device__ float g_tfull[RT*Hh];
__device__ float g_tmax[RT*Mm];
__device__ unsigned g_barctr;

// paired-transposed index for state buffers: element (k=j, b)
__device__ __forceinline__ int ptidx(int j, int b) { return ((j >> 1) * 64) + 2 * b + (j & 1); }

// ---------------- embedding gather ----------------
__global__ void gather_emb(const int* __restrict__ tok, const float* __restrict__ emb,
                           float* __restrict__ out, int L)
{
    int r = blockIdx.x;
    int s = r >> 5, b = r & 31;
    int token = tok[b * L + s];
    const float* srcp = emb + (long)token * Ee;
    float* dst = out + (long)r * Ee;
    for (int e = threadIdx.x; e < Ee; e += blockDim.x) dst[e] = srcp[e];
}

// ================= tensor-core bf16x3 multi-GEMM =================
// C = A @ B^T (A,B fp32, bf16 hi/lo split, 3 MMA passes).
// blockIdx.z selects one of up to 5 (B, C, bias, mode) problem instances sharing A.
// modes: 0: C[row*ldc+col] (+bias)
//        2: + add1[row*ldc+col] + add2[(row&31)*ldc+col]
//        3: logits scatter C[(row&31)*T*V + (row>>5)*V + col]
//        4: trans-flat C[((row>>5)*Hh + col)*32 + (row&31)] (+bias)
//        5: dual tanh: C[(row&31)*Hh+col]=tanh(v) and add1[ptidx(col,row&31)]=tanh(v)
struct MultiGemm {
    const float* A;
    const float* B[5];
    float*       C[5];
    const float* bias[5];
    const float* add1[5];
    const float* add2[5];
    int mode[5];
    int M, N, K, lda, ldb, ldc;
    int transA;   // A element (r,k) = A[ptidx(k,r)]
};

#define TBM 128
#define TBN 128
#define TBK 16
#define SKS 24

__device__ __forceinline__ uint32_t smem_u32(const void* p) {
    return (uint32_t)__cvta_generic_to_shared(p);
}
__device__ __forceinline__ void ldsm4(uint32_t &r0, uint32_t &r1, uint32_t &r2, uint32_t &r3, uint32_t a) {
    asm volatile("ldmatrix.sync.aligned.m8n8.x4.shared.b16 {%0,%1,%2,%3}, [%4];\n"
        : "=r"(r0), "=r"(r1), "=r"(r2), "=r"(r3) : "r"(a));
}
__device__ __forceinline__ void mma_bf16(float* c, const uint32_t* a, uint32_t b0, uint32_t b1) {
    asm volatile("mma.sync.aligned.m16n8k16.row.col.f32.bf16.bf16.f32 "
        "{%0,%1,%2,%3},{%4,%5,%6,%7},{%8,%9},{%0,%1,%2,%3};\n"
        : "+f"(c[0]), "+f"(c[1]), "+f"(c[2]), "+f"(c[3])
        : "r"(a[0]), "r"(a[1]), "r"(a[2]), "r"(a[3]), "r"(b0), "r"(b1));
}

__global__ __launch_bounds__(256, 2)
void mma_gemm(MultiGemm g)
{
    __shared__ __align__(16) __nv_bfloat16 Ah[TBM*SKS];
    __shared__ __align__(16) __nv_bfloat16 Al[TBM*SKS];
    __shared__ __align__(16) __nv_bfloat16 Bh[TBN*SKS];
    __shared__ __align__(16) __nv_bfloat16 Bl[TBN*SKS];

    int z = blockIdx.z;
    const float* A  = g.A;
    const float* Bm = g.B[z];
    float* C        = g.C[z];
    const float* bias = g.bias[z];
    const float* add1 = g.add1[z];
    const float* add2 = g.add2[z];
    int mode = g.mode[z];
    int M = g.M, N = g.N, K = g.K, lda = g.lda, ldb = g.ldb, ldc = g.ldc;

    int t = threadIdx.x, lane = t & 31, wid = t >> 5;
    int wm = wid & 1, wn = wid >> 1;
    int m0 = blockIdx.y * TBM, n0 = blockIdx.x * TBN;

    float acc[4][4][4];
#pragma unroll
    for (int i = 0; i < 4; i++)
#pragma unroll
        for (int j = 0; j < 4; j++)
#pragma unroll
            for (int c = 0; c < 4; c++) acc[i][j][c] = 0.f;

    int sel = lane >> 3, l7 = lane & 7;
    int ar = (sel & 1) * 8 + l7;
    int ac = (sel >> 1) * 8;
    int br = (sel >> 1) * 8 + l7;
    int bc = (sel & 1) * 8;

    int KT = (K + TBK - 1) / TBK;
    float4 pa[2], pb[2];

    auto loadA = [&](int kt, float4 v[2]) {
#pragma unroll
        for (int i = 0; i < 2; i++) {
            int idx = t + i * 256;
            int row = idx >> 2, k4 = idx & 3;
            int gr = m0 + row, gk = kt * TBK + k4 * 4;
            float4 x = {0.f, 0.f, 0.f, 0.f};
            if (gr < M) {
                if (!g.transA) {
                    if (gk < K) x = *(const float4*)(A + (size_t)gr * lda + gk);
                } else {
                    float* xf = (float*)&x;
#pragma unroll
                    for (int c = 0; c < 4; c++) {
                        int kk = gk + c;
                        if (kk < K) xf[c] = A[ptidx(kk, gr)];
                    }
                }
            }
            v[i] = x;
        }
    };
    auto loadB = [&](int kt, float4 v[2]) {
#pragma unroll
        for (int i = 0; i < 2; i++) {
            int idx = t + i * 256;
            int row = idx >> 2, k4 = idx & 3;
            int gr = n0 + row, gk = kt * TBK + k4 * 4;
            float4 x = {0.f, 0.f, 0.f, 0.f};
            if (gr < N && gk < K) x = *(const float4*)(Bm + (size_t)gr * ldb + gk);
            v[i] = x;
        }
    };
    auto storeT = [&](__nv_bfloat16* Sh, __nv_bfloat16* Sl, const float4 v[2]) {
#pragma unroll
        for (int i = 0; i < 2; i++) {
            int idx = t + i * 256;
            int row = idx >> 2, k4 = idx & 3;
            const float* f = (const float*)&v[i];
#pragma unroll
            for (int c = 0; c < 4; c++) {
                float x = f[c];
                __nv_bfloat16 h = __float2bfloat16(x);
                __nv_bfloat16 l = __float2bfloat16(x - __bfloat162float(h));
                Sh[row * SKS + k4 * 4 + c] = h;
                Sl[row * SKS + k4 * 4 + c] = l;
            }
        }
    };

    loadA(0, pa);
    loadB(0, pb);

    for (int kt = 0; kt < KT; kt++) {
        __syncthreads();
        storeT(Ah, Al, pa);
        storeT(Bh, Bl, pb);
        __syncthreads();
        if (kt + 1 < KT) { loadA(kt + 1, pa); loadB(kt + 1, pb); }
        uint32_t af[4][4], bh[4][2], bl[4][2];
#pragma unroll
        for (int mi = 0; mi < 4; mi++) {
            uint32_t addr = smem_u32(&Ah[(wm * 64 + mi * 16 + ar) * SKS + ac]);
            ldsm4(af[mi][0], af[mi][1], af[mi][2], af[mi][3], addr);
        }
#pragma unroll
        for (int p = 0; p < 2; p++) {
            uint32_t addr = smem_u32(&Bh[(wn * 32 + p * 16 + br) * SKS + bc]);
            uint32_t r0, r1, r2, r3;
            ldsm4(r0, r1, r2, r3, addr);
            bh[2*p][0] = r0; bh[2*p][1] = r1; bh[2*p+1][0] = r2; bh[2*p+1][1] = r3;
            addr = smem_u32(&Bl[(wn * 32 + p * 16 + br) * SKS + bc]);
            ldsm4(r0, r1, r2, r3, addr);
            bl[2*p][0] = r0; bl[2*p][1] = r1; bl[2*p+1][0] = r2; bl[2*p+1][1] = r3;
        }
#pragma unroll
        for (int mi = 0; mi < 4; mi++)
#pragma unroll
            for (int ni = 0; ni < 4; ni++) {
                mma_bf16(acc[mi][ni], af[mi], bh[ni][0], bh[ni][1]);
                mma_bf16(acc[mi][ni], af[mi], bl[ni][0], bl[ni][1]);
            }
#pragma unroll
        for (int mi = 0; mi < 4; mi++) {
            uint32_t addr = smem_u32(&Al[(wm * 64 + mi * 16 + ar) * SKS + ac]);
            ldsm4(af[mi][0], af[mi][1], af[mi][2], af[mi][3], addr);
        }
#pragma unroll
        for (int mi = 0; mi < 4; mi++)
#pragma unroll
            for (int ni = 0; ni < 4; ni++)
                mma_bf16(acc[mi][ni], af[mi], bh[ni][0], bh[ni][1]);
    }

    int gq = lane >> 2, tig = lane & 3;
#pragma unroll
    for (int mi = 0; mi < 4; mi++) {
#pragma unroll
        for (int ni = 0; ni < 4; ni++) {
#pragma unroll
            for (int c = 0; c < 4; c++) {
                int row = m0 + wm * 64 + mi * 16 + gq + ((c >> 1) ? 8 : 0);
                int col = n0 + wn * 32 + ni * 8 + tig * 2 + (c & 1);
                if (row >= M || col >= N) continue;
                float v = acc[mi][ni][c];
                if (mode == 0) {
                    if (bias) v += bias[col];
                    C[(size_t)row * ldc + col] = v;
                } else if (mode == 2) {
                    v += add1[(size_t)row * ldc + col] + add2[(size_t)(row & 31) * ldc + col];
                    C[(size_t)row * ldc + col] = v;
                } else if (mode == 3) {
                    int b = row & 31, ti = row >> 5;
                    C[(size_t)b * (Tt * Vv) + (size_t)ti * Vv + col] = v;
                } else if (mode == 4) {
                    if (bias) v += bias[col];
                    int b = row & 31, ti = row >> 5;
                    C[((size_t)ti * Hh + col) * 32 + b] = v;
                } else { // 5
                    int b = row & 31;
                    float tv = tanhf(v);
                    C[(size_t)b * Hh + col] = tv;            // Sst[0]
                    ((float*)add1)[ptidx(col, b)] = tv;      // s0T paired
                }
            }
        }
    }
}

// ================= persistent recurrence =================
__device__ __forceinline__ unsigned long long pack2(float2 v) {
    unsigned long long r;
    asm("mov.b64 %0, {%1, %2};" : "=l"(r) : "f"(v.x), "f"(v.y));
    return r;
}
__device__ __forceinline__ unsigned long long pack2f(float a, float b) {
    unsigned long long r;
    asm("mov.b64 %0, {%1, %2};" : "=l"(r) : "f"(a), "f"(b));
    return r;
}
__device__ __forceinline__ float2 unpack2(unsigned long long v) {
    float2 r;
    asm("mov.b64 {%0, %1}, %2;" : "=f"(r.x), "=f"(r.y) : "l"(v));
    return r;
}
__device__ __forceinline__ void ffma2(unsigned long long &acc, unsigned long long a, unsigned long long b) {
    asm("fma.rn.f32x2 %0, %1, %2, %0;" : "+l"(acc) : "l"(a), "l"(b));
}

__device__ __forceinline__ void gbar(unsigned &tgt) {
    __threadfence();
    __syncthreads();
    if (threadIdx.x == 0) {
        atomicAdd(&g_barctr, 1u);
        unsigned v;
        do {
            asm volatile("ld.acquire.gpu.global.u32 %0, [%1];" : "=r"(v) : "l"(&g_barctr) : "memory");
            if (v >= tgt) break;
            __nanosleep(32);
        } while (true);
    }
    __syncthreads();
    tgt += gridDim.x;
}

// smem: usr[8000] usz[8000] usc[8000] red[4096] zs[256]  = 28352 floats
#define SMEM_RECUR (28352*4)

__global__ __launch_bounds__(256, 1)
void recur_persist(float* __restrict__ hT2, float* __restrict__ rhT2,
    const float* __restrict__ GUr, const float* __restrict__ GUz, const float* __restrict__ GUc,
    const float* __restrict__ Xr, const float* __restrict__ Xz, const float* __restrict__ Xc,
    const float* __restrict__ ctxR, const float* __restrict__ ctxZ, const float* __restrict__ ctxC,
    float* __restrict__ Sst, int nsteps)
{
    extern __shared__ float sm[];
    float* usr = sm;
    float* usz = sm + 8000;
    float* usc = sm + 16000;
    float* red = sm + 24000;
    float* zs  = sm + 28096;
    int tid = threadIdx.x, lane = tid & 31, w = tid >> 5;
    int jbase = blockIdx.x * NCOLS;

    // load this block's U rows into smem once
    for (int i4 = tid; i4 < 2000; i4 += 256) {
        int row = i4 / 250, k4 = (i4 % 250) * 4;
        *(float4*)(usr + row * 1000 + k4) = *(const float4*)(GUr + (size_t)(jbase + row) * 1000 + k4);
        *(float4*)(usz + row * 1000 + k4) = *(const float4*)(GUz + (size_t)(jbase + row) * 1000 + k4);
        *(float4*)(usc + row * 1000 + k4) = *(const float4*)(GUc + (size_t)(jbase + row) * 1000 + k4);
    }
    __syncthreads();

    // per-warp contiguous kk2 slices (even lengths, even offsets -> 16B-aligned U reads)
    const int offs[8] = {0, 64, 128, 192, 256, 318, 380, 440};
    const int lens[8] = {64, 64, 64, 64, 62, 62, 60, 60};
    int off = offs[w], len = lens[w];
    unsigned tgt = gridDim.x;

    for (int step = 0; step < nsteps; step++) {
        // ---------- phase A: r,z gates ----------
        {
            unsigned long long acc[16];
#pragma unroll
            for (int p = 0; p < 16; p++) acc[p] = 0ull;
            float2 h0 = *(const float2*)(hT2 + (off) * 64 + 2 * lane);
            float2 h1 = *(const float2*)(hT2 + (off + 1) * 64 + 2 * lane);
            for (int i = 0; i < len; i += 2) {
                float2 n0, n1;
                if (i + 2 < len) {
                    n0 = *(const float2*)(hT2 + (off + i + 2) * 64 + 2 * lane);
                    n1 = *(const float2*)(hT2 + (off + i + 3) * 64 + 2 * lane);
                }
                int k0 = (off + i) * 2;
                unsigned long long h0p = pack2(h0), h1p = pack2(h1);
#pragma unroll
                for (int p = 0; p < 16; p++) {
                    const float* us = (p & 1) ? usz : usr;
                    float4 u = *(const float4*)(us + (p >> 1) * 1000 + k0);
                    ffma2(acc[p], h0p, pack2f(u.x, u.y));
                    ffma2(acc[p], h1p, pack2f(u.z, u.w));
                }
                h0 = n0; h1 = n1;
            }
#pragma unroll
            for (int p = 0; p < 16; p++) {
                float2 a = unpack2(acc[p]);
                red[w * 512 + p * 32 + lane] = a.x + a.y;
            }
            __syncthreads();
            for (int o = tid; o < 512; o += 256) {
                int p = o >> 5, b = o & 31;
                int col = p >> 1, gate = p & 1;
                int jg = jbase + col;
                float s = 0.f;
#pragma unroll
                for (int ww = 0; ww < 8; ww++) s += red[ww * 512 + p * 32 + b];
                const float* X = gate ? Xz : Xr;
                float pre = X[((size_t)step * Hh + jg) * 32 + b] + s;
                const float* ctx = gate ? ctxZ : ctxR;
                if (ctx) pre += ctx[jg * 32 + b];
                float sg = 1.f / (1.f + __expf(-pre));
                if (gate == 0) {
                    int hi = ptidx(jg, b);
                    rhT2[hi] = sg * hT2[hi];
                } else {
                    zs[col * 32 + b] = sg;
                }
            }
        }
        gbar(tgt);
        // ---------- phase B: candidate + blend ----------
        {
            unsigned long long acc[8];
#pragma unroll
            for (int p = 0; p < 8; p++) acc[p] = 0ull;
            float2 h0 = *(const float2*)(rhT2 + (off) * 64 + 2 * lane);
            float2 h1 = *(const float2*)(rhT2 + (off + 1) * 64 + 2 * lane);
            for (int i = 0; i < len; i += 2) {
                float2 n0, n1;
                if (i + 2 < len) {
                    n0 = *(const float2*)(rhT2 + (off + i + 2) * 64 + 2 * lane);
                    n1 = *(const float2*)(rhT2 + (off + i + 3) * 64 + 2 * lane);
                }
                int k0 = (off + i) * 2;
                unsigned long long h0p = pack2(h0), h1p = pack2(h1);
#pragma unroll
                for (int p = 0; p < 8; p++) {
                    float4 u = *(const float4*)(usc + p * 1000 + k0);
                    ffma2(acc[p], h0p, pack2f(u.x, u.y));
                    ffma2(acc[p], h1p, pack2f(u.z, u.w));
                }
                h0 = n0; h1 = n1;
            }
            __syncthreads();   // zs still needed; protect red reuse
#pragma unroll
            for (int p = 0; p < 8; p++) {
                float2 a = unpack2(acc[p]);
                red[w * 256 + p * 32 + lane] = a.x + a.y;
            }
            __syncthreads();
            {
                int col = tid >> 5, b = tid & 31;
                int jg = jbase + col;
                float s = 0.f;
#pragma unroll
                for (int ww = 0; ww < 8; ww++) s += red[ww * 256 + col * 32 + b];
                float pre = Xc[((size_t)step * Hh + jg) * 32 + b] + s;
                if (ctxC) pre += ctxC[jg * 32 + b];
                float cand = tanhf(pre);
                float zv = zs[col * 32 + b];
                int hi = ptidx(jg, b);
                float hv = hT2[hi];
                float hn = (1.f - zv) * hv + zv * cand;
                hT2[hi] = hn;
                if (Sst != nullptr && step + 1 < nsteps)
                    Sst[((size_t)(step + 1) * 32 + b) * Hh + jg] = hn;
            }
        }
        gbar(tgt);
    }
}

// ---------------- maxout ----------------
__global__ void maxout_k(const float* __restrict__ tf, float* __restrict__ tm)
{
    int i = blockIdx.x * blockDim.x + threadIdx.x;
    int total = RT * Mm;
    if (i < total) {
        int r = i / Mm, m = i - r * Mm;
        tm[i] = fmaxf(tf[r * Hh + 2 * m], tf[r * Hh + 2 * m + 1]);
    }
}

// ---------------- host orchestration ----------------
extern "C" void kernel_launch(void* const* d_in, const int* in_sizes, int n_in,
                              void* d_out, int out_size)
{
    const int*   src     = (const int*)d_in[0];
    const int*   tgt     = (const int*)d_in[1];
    const float* src_emb = (const float*)d_in[3];
    const float* tgt_emb = (const float*)d_in[4];
    const float* enc_W   = (const float*)d_in[5];
    const float* enc_Wz  = (const float*)d_in[6];
    const float* enc_Wr  = (const float*)d_in[7];
    const float* enc_U   = (const float*)d_in[8];
    const float* enc_Uz  = (const float*)d_in[9];
    const float* enc_Ur  = (const float*)d_in[10];
    const float* enc_b   = (const float*)d_in[11];
    const float* enc_bz  = (const float*)d_in[12];
    const float* enc_br  = (const float*)d_in[13];
    const float* dec_W   = (const float*)d_in[14];
    const float* dec_Wz  = (const float*)d_in[15];
    const float* dec_Wr  = (const float*)d_in[16];
    const float* dec_U   = (const float*)d_in[17];
    const float* dec_Uz  = (const float*)d_in[18];
    const float* dec_Ur  = (const float*)d_in[19];
    const float* dec_C   = (const float*)d_in[20];
    const float* dec_Cz  = (const float*)d_in[21];
    const float* dec_Cr  = (const float*)d_in[22];
    const float* dec_b   = (const float*)d_in[23];
    const float* dec_bz  = (const float*)d_in[24];
    const float* dec_br  = (const float*)d_in[25];
    const float* W_s     = (const float*)d_in[26];
    const float* U_o     = (const float*)d_in[27];
    const float* V_o     = (const float*)d_in[28];
    const float* C_o     = (const float*)d_in[29];
    const float* W_o     = (const float*)d_in[30];
    float* out = (float*)d_out;

    float *Xsrc, *Ytgt, *Xr, *Xz, *Xc, *Yr, *Yz, *Yc, *Yo;
    float *hT2, *s0T, *rhT2, *cCrT, *cCzT, *cCT, *cCo, *Sst, *tfull, *tmax;
    unsigned* barctr;
    cudaGetSymbolAddress((void**)&Xsrc, g_Xsrc);
    cudaGetSymbolAddress((void**)&Ytgt, g_Ytgt);
    cudaGetSymbolAddress((void**)&Xr, g_Xr);
    cudaGetSymbolAddress((void**)&Xz, g_Xz);
    cudaGetSymbolAddress((void**)&Xc, g_Xc);
    cudaGetSymbolAddress((void**)&Yr, g_Yr);
    cudaGetSymbolAddress((void**)&Yz, g_Yz);
    cudaGetSymbolAddress((void**)&Yc, g_Yc);
    cudaGetSymbolAddress((void**)&Yo, g_Yo);
    cudaGetSymbolAddress((void**)&hT2, g_hT2);
    cudaGetSymbolAddress((void**)&s0T, g_s0T);
    cudaGetSymbolAddress((void**)&rhT2, g_rhT2);
    cudaGetSymbolAddress((void**)&cCrT, g_cCrT);
    cudaGetSymbolAddress((void**)&cCzT, g_cCzT);
    cudaGetSymbolAddress((void**)&cCT,  g_cCT);
    cudaGetSymbolAddress((void**)&cCo, g_cCo);
    cudaGetSymbolAddress((void**)&Sst, g_S);
    cudaGetSymbolAddress((void**)&tfull, g_tfull);
    cudaGetSymbolAddress((void**)&tmax, g_tmax);
    cudaGetSymbolAddress((void**)&barctr, g_barctr);

    cudaFuncSetAttribute(recur_persist, cudaFuncAttributeMaxDynamicSharedMemorySize, SMEM_RECUR);

    // ---- phase 0: gathers + fused input projections ----
    gather_emb<<<RS, 128>>>(src, src_emb, Xsrc, Ss);
    gather_emb<<<RT, 128>>>(tgt, tgt_emb, Ytgt, Tt);

    {
        MultiGemm g = {};
        g.A = Xsrc; g.M = RS; g.N = Hh; g.K = Ee; g.lda = Ee; g.ldb = Ee; g.ldc = Hh; g.transA = 0;
        g.B[0] = enc_Wr; g.C[0] = Xr; g.bias[0] = enc_br; g.mode[0] = 4;
        g.B[1] = enc_Wz; g.C[1] = Xz; g.bias[1] = enc_bz; g.mode[1] = 4;
        g.B[2] = enc_W;  g.C[2] = Xc; g.bias[2] = enc_b;  g.mode[2] = 4;
        dim3 gr((Hh + TBN - 1) / TBN, (RS + TBM - 1) / TBM, 3);
        mma_gemm<<<gr, 256>>>(g);
    }
    {
        MultiGemm g = {};
        g.A = Ytgt; g.M = RT; g.N = Hh; g.K = Ee; g.lda = Ee; g.ldb = Ee; g.ldc = Hh; g.transA = 0;
        g.B[0] = dec_Wr; g.C[0] = Yr; g.bias[0] = dec_br; g.mode[0] = 4;
        g.B[1] = dec_Wz; g.C[1] = Yz; g.bias[1] = dec_bz; g.mode[1] = 4;
        g.B[2] = dec_W;  g.C[2] = Yc; g.bias[2] = dec_b;  g.mode[2] = 4;
        g.B[3] = V_o;    g.C[3] = Yo; g.bias[3] = nullptr; g.mode[3] = 0;
        dim3 gr((Hh + TBN - 1) / TBN, (RT + TBM - 1) / TBM, 4);
        mma_gemm<<<gr, 256>>>(g);
    }

    // ---- phase 1: encoder recurrence (persistent) ----
    cudaMemsetAsync(hT2, 0, (size_t)Hh * Bb * sizeof(float));
    cudaMemsetAsync(barctr, 0, sizeof(unsigned));
    recur_persist<<<NBLK, 256, SMEM_RECUR>>>(hT2, rhT2,
        enc_Ur, enc_Uz, enc_U, Xr, Xz, Xc,
        nullptr, nullptr, nullptr, nullptr, Ss);

    // ---- phase 2: fixed context projections (A = c in paired layout) ----
    {
        MultiGemm g = {};
        g.A = hT2; g.M = Bb; g.N = Hh; g.K = Hh; g.lda = Hh; g.ldb = Hh; g.ldc = Hh; g.transA = 1;
        g.B[0] = W_s;    g.C[0] = Sst;  g.add1[0] = s0T; g.mode[0] = 5;   // Sst[0] + s0T
        g.B[1] = dec_Cr; g.C[1] = cCrT; g.mode[1] = 4;
        g.B[2] = dec_Cz; g.C[2] = cCzT; g.mode[2] = 4;
        g.B[3] = dec_C;  g.C[3] = cCT;  g.mode[3] = 4;
        g.B[4] = C_o;    g.C[4] = cCo;  g.mode[4] = 0;
        dim3 gr((Hh + TBN - 1) / TBN, 1, 5);
        mma_gemm<<<gr, 256>>>(g);
    }

    // ---- phase 3: decoder recurrence (persistent, stores pre-update states) ----
    cudaMemsetAsync(barctr, 0, sizeof(unsigned));
    recur_persist<<<NBLK, 256, SMEM_RECUR>>>(s0T, rhT2,
        dec_Ur, dec_Uz, dec_U, Yr, Yz, Yc,
        cCrT, cCzT, cCT, Sst, Tt);

    // ---- phase 4: output layer ----
    {
        MultiGemm g = {};
        g.A = Sst; g.M = RT; g.N = Hh; g.K = Hh; g.lda = Hh; g.ldb = Hh; g.ldc = Hh; g.transA = 0;
        g.B[0] = U_o; g.C[0] = tfull; g.add1[0] = Yo; g.add2[0] = cCo; g.mode[0] = 2;
        dim3 gr((Hh + TBN - 1) / TBN, (RT + TBM - 1) / TBM, 1);
        mma_gemm<<<gr, 256>>>(g);
    }
    maxout_k<<<(RT * Mm + 255) / 256, 256>>>(tfull, tmax);
    {
        MultiGemm g = {};
        g.A = tmax; g.M = RT; g.N = Vv; g.K = Mm; g.lda = Mm; g.ldb = Mm; g.ldc = Vv; g.transA = 0;
        g.B[0] = W_o; g.C[0] = out; g.mode[0] = 3;
        dim3 gr((Vv + TBN - 1) / TBN, (RT + TBM - 1) / TBM, 1);
        mma_gemm<<<gr, 256>>>(g);
    }
}

// round 6
// speedup vs baseline: 3.1125x; 1.0037x over previous
#include <cuda_runtime.h>
#include <cuda_bf16.h>
#include <math.h>
#include <stdint.h>

#define Bb 32
#define Ss 24
#define Tt 24
#define Vv 30000
#define Ee 620
#define Hh 1000
#define Mm 500
#define RS (Ss*Bb)   /* 768 */
#define RT (Tt*Bb)   /* 768 */
#define NBLK 125
#define NCOLS 8

#define K3E 1920   /* 3*620=1860 -> pad 1920 */
#define K3H 3072   /* 3*1000=3000 -> pad 3072 */
#define K3M 1536   /* 3*500=1500 -> pad 1536 */

// ---------------- fp32 scratch ----------------
__device__ float g_Xsrc[RS*Ee];
__device__ float g_Ytgt[RT*Ee];
__device__ float g_Xr[RS*Hh];    // [t][j][b]
__device__ float g_Xz[RS*Hh];
__device__ float g_Xc[RS*Hh];
__device__ float g_Yr[RT*Hh];
__device__ float g_Yz[RT*Hh];
__device__ float g_Yc[RT*Hh];
__device__ float g_Yo[RT*Hh];    // normal [row][2M]
__device__ float g_hT2[Hh*Bb];   // paired transposed state
__device__ float g_s0T[Hh*Bb];
__device__ float g_rhT2[Hh*Bb];
__device__ float g_cCrT[Hh*Bb];
__device__ float g_cCzT[Hh*Bb];
__device__ float g_cCT [Hh*Bb];
__device__ float g_cCo[Bb*Hh];
__device__ float g_S[RT*Hh];     // decoder pre-update states [t*32+b][H]
__device__ float g_tfull[RT*Hh];
__device__ float g_tmax[RT*Mm];
__device__ unsigned g_barctr;

// ---------------- bf16 tripled operands ----------------
__device__ __nv_bfloat16 g3_eWr[Hh*K3E];
__device__ __nv_bfloat16 g3_eWz[Hh*K3E];
__device__ __nv_bfloat16 g3_eW [Hh*K3E];
__device__ __nv_bfloat16 g3_dWr[Hh*K3E];
__device__ __nv_bfloat16 g3_dWz[Hh*K3E];
__device__ __nv_bfloat16 g3_dW [Hh*K3E];
__device__ __nv_bfloat16 g3_Vo [Hh*K3E];
__device__ __nv_bfloat16 g3_Ws [Hh*K3H];
__device__ __nv_bfloat16 g3_Cr [Hh*K3H];
__device__ __nv_bfloat16 g3_Cz [Hh*K3H];
__device__ __nv_bfloat16 g3_C  [Hh*K3H];
__device__ __nv_bfloat16 g3_Co [Hh*K3H];
__device__ __nv_bfloat16 g3_Uo [Hh*K3H];
__device__ __nv_bfloat16 g3_Wo [Vv*K3M];
__device__ __nv_bfloat16 g3_X  [RS*K3E];
__device__ __nv_bfloat16 g3_Y  [RT*K3E];
__device__ __nv_bfloat16 g3_cT [Bb*K3H];
__device__ __nv_bfloat16 g3_S  [RT*K3H];
__device__ __nv_bfloat16 g3_T  [RT*K3M];

__device__ __forceinline__ int ptidx(int j, int b) { return ((j >> 1) * 64) + 2 * b + (j & 1); }

// ---------------- embedding gather ----------------
__global__ void gather_emb(const int* __restrict__ tok, const float* __restrict__ emb,
                           float* __restrict__ out, int L)
{
    int r = blockIdx.x;
    int s = r >> 5, b = r & 31;
    int token = tok[b * L + s];
    const float* srcp = emb + (long)token * Ee;
    float* dst = out + (long)r * Ee;
    for (int e = threadIdx.x; e < Ee; e += blockDim.x) dst[e] = srcp[e];
}

// ---------------- fp32 -> tripled bf16 convert ----------------
// typeB=1 (B operand): [hi | hi | lo];  typeB=0 (A operand): [hi | lo | hi]
// paired=1: src element (r,k) at ptidx(k,r)
struct ConvEntry { const float* src; __nv_bfloat16* dst; int R, K, K3p, typeB, paired; };
struct ConvBatch { ConvEntry e[8]; };

__global__ void conv_k(ConvBatch cb)
{
    ConvEntry E = cb.e[blockIdx.y];
    int per = E.K3p >> 3;
    int total = E.R * per;
    int i = blockIdx.x * 256 + threadIdx.x;
    if (i >= total) return;
    int r = i / per, c8 = (i - r * per) * 8;
    const float* s = E.src + (size_t)r * E.K;
    __nv_bfloat16 o[8];
#pragma unroll
    for (int j = 0; j < 8; j++) {
        int k3 = c8 + j;
        int K = E.K;
        float v = 0.f; int wantLo = 0;
        int k = -1;
        if (k3 < K)          { k = k3;         wantLo = 0; }
        else if (k3 < 2 * K) { k = k3 - K;     wantLo = E.typeB ? 0 : 1; }
        else if (k3 < 3 * K) { k = k3 - 2 * K; wantLo = E.typeB ? 1 : 0; }
        if (k >= 0) v = E.paired ? E.src[((k >> 1) << 6) + 2 * r + (k & 1)] : s[k];
        __nv_bfloat16 h = __float2bfloat16(v);
        o[j] = wantLo ? __float2bfloat16(v - __bfloat162float(h)) : h;
    }
    *(float4*)(E.dst + (size_t)r * E.K3p + c8) = *(float4*)o;
}

// ================= bf16 GEMM (cp.async double-buffered) =================
// C = A3 @ B3^T over tripled-K.  blockIdx.z selects instance.
// modes: 0: C[row*ldc+col] (+bias)
//        2: + add1[row*ldc+col] + add2[(row&31)*ldc+col]
//        3: logits scatter C[(row&31)*T*V + (row>>5)*V + col]
//        4: trans-flat C[((row>>5)*Hh + col)*32 + (row&31)] (+bias)
//        5: dual tanh: C[(row&31)*Hh+col]=tanh(v), add1[ptidx(col,row&31)]=tanh(v)
struct MultiGemm {
    const __nv_bfloat16* A3;
    const __nv_bfloat16* B3[5];
    float*       C[5];
    const float* bias[5];
    const float* add1[5];
    const float* add2[5];
    int mode[5];
    int M, N, K3p, ldc;
};

#define GBM 128
#define GBN 128
#define GBK 64
#define GSK 72
#define GSTAGE_ELEMS (128*GSK)
#define GSMEM_BYTES (4*GSTAGE_ELEMS*2)

__device__ __forceinline__ uint32_t smem_u32(const void* p) {
    return (uint32_t)__cvta_generic_to_shared(p);
}
__device__ __forceinline__ void ldsm4(uint32_t &r0, uint32_t &r1, uint32_t &r2, uint32_t &r3, uint32_t a) {
    asm volatile("ldmatrix.sync.aligned.m8n8.x4.shared.b16 {%0,%1,%2,%3}, [%4];\n"
        : "=r"(r0), "=r"(r1), "=r"(r2), "=r"(r3) : "r"(a));
}
__device__ __forceinline__ void mma_bf16(float* c, const uint32_t* a, uint32_t b0, uint32_t b1) {
    asm volatile("mma.sync.aligned.m16n8k16.row.col.f32.bf16.bf16.f32 "
        "{%0,%1,%2,%3},{%4,%5,%6,%7},{%8,%9},{%0,%1,%2,%3};\n"
        : "+f"(c[0]), "+f"(c[1]), "+f"(c[2]), "+f"(c[3])
        : "r"(a[0]), "r"(a[1]), "r"(a[2]), "r"(a[3]), "r"(b0), "r"(b1));
}
__device__ __forceinline__ void cpasync16(uint32_t daddr, const void* src, int sbytes) {
    asm volatile("cp.async.cg.shared.global [%0], [%1], 16, %2;\n"
        :: "r"(daddr), "l"(src), "r"(sbytes));
}

__global__ __launch_bounds__(256, 2)
void bf16_gemm(MultiGemm g)
{
    extern __shared__ __nv_bfloat16 smem[];
    __nv_bfloat16* sA = smem;
    __nv_bfloat16* sB = smem + 2 * GSTAGE_ELEMS;

    int z = blockIdx.z;
    const __nv_bfloat16* A  = g.A3;
    const __nv_bfloat16* Bm = g.B3[z];
    float* C          = g.C[z];
    const float* bias = g.bias[z];
    const float* add1 = g.add1[z];
    const float* add2 = g.add2[z];
    int mode = g.mode[z];
    int M = g.M, N = g.N, K3p = g.K3p, ldc = g.ldc;

    int t = threadIdx.x, lane = t & 31, wid = t >> 5;
    int wm = wid & 1, wn = wid >> 1;
    int m0 = blockIdx.y * GBM, n0 = blockIdx.x * GBN;

    float acc[4][4][4];
#pragma unroll
    for (int i = 0; i < 4; i++)
#pragma unroll
        for (int j = 0; j < 4; j++)
#pragma unroll
            for (int c = 0; c < 4; c++) acc[i][j][c] = 0.f;

    int sel = lane >> 3, l7 = lane & 7;
    int ar = (sel & 1) * 8 + l7;
    int ac = (sel >> 1) * 8;
    int br = (sel >> 1) * 8 + l7;
    int bc = (sel & 1) * 8;

    int KT = K3p / GBK;

    // stage loader
    auto loadStage = [&](int kt, int st) {
        int kbase = kt * GBK;
#pragma unroll
        for (int i = 0; i < 4; i++) {
            int idx = t + i * 256;          // 0..1023
            int row = idx >> 3, sg = idx & 7;
            {
                int gr = m0 + row;
                int ok = (gr < M);
                const __nv_bfloat16* src = A + (size_t)(ok ? gr : 0) * K3p + kbase + sg * 8;
                cpasync16(smem_u32(&sA[st * GSTAGE_ELEMS + row * GSK + sg * 8]), src, ok ? 16 : 0);
            }
            {
                int gr = n0 + row;
                int ok = (gr < N);
                const __nv_bfloat16* src = Bm + (size_t)(ok ? gr : 0) * K3p + kbase + sg * 8;
                cpasync16(smem_u32(&sB[st * GSTAGE_ELEMS + row * GSK + sg * 8]), src, ok ? 16 : 0);
            }
        }
        asm volatile("cp.async.commit_group;\n");
    };

    loadStage(0, 0);

    for (int kt = 0; kt < KT; kt++) {
        int st = kt & 1;
        if (kt + 1 < KT) {
            loadStage(kt + 1, st ^ 1);
            asm volatile("cp.async.wait_group 1;\n");
        } else {
            asm volatile("cp.async.wait_group 0;\n");
        }
        __syncthreads();

        const __nv_bfloat16* a_st = sA + st * GSTAGE_ELEMS;
        const __nv_bfloat16* b_st = sB + st * GSTAGE_ELEMS;
#pragma unroll
        for (int kh = 0; kh < 4; kh++) {
            uint32_t af[4][4], bf[4][2];
#pragma unroll
            for (int mi = 0; mi < 4; mi++) {
                uint32_t addr = smem_u32(&a_st[(wm * 64 + mi * 16 + ar) * GSK + kh * 16 + ac]);
                ldsm4(af[mi][0], af[mi][1], af[mi][2], af[mi][3], addr);
            }
#pragma unroll
            for (int p = 0; p < 2; p++) {
                uint32_t r0, r1, r2, r3;
                uint32_t addr = smem_u32(&b_st[(wn * 32 + p * 16 + br) * GSK + kh * 16 + bc]);
                ldsm4(r0, r1, r2, r3, addr);
                bf[2*p][0] = r0; bf[2*p][1] = r1; bf[2*p+1][0] = r2; bf[2*p+1][1] = r3;
            }
#pragma unroll
            for (int mi = 0; mi < 4; mi++)
#pragma unroll
                for (int ni = 0; ni < 4; ni++)
                    mma_bf16(acc[mi][ni], af[mi], bf[ni][0], bf[ni][1]);
        }
        __syncthreads();
    }

    int gq = lane >> 2, tig = lane & 3;
#pragma unroll
    for (int mi = 0; mi < 4; mi++) {
#pragma unroll
        for (int ni = 0; ni < 4; ni++) {
#pragma unroll
            for (int c = 0; c < 4; c++) {
                int row = m0 + wm * 64 + mi * 16 + gq + ((c >> 1) ? 8 : 0);
                int col = n0 + wn * 32 + ni * 8 + tig * 2 + (c & 1);
                if (row >= M || col >= N) continue;
                float v = acc[mi][ni][c];
                if (mode == 0) {
                    if (bias) v += bias[col];
                    C[(size_t)row * ldc + col] = v;
                } else if (mode == 2) {
                    v += add1[(size_t)row * ldc + col] + add2[(size_t)(row & 31) * ldc + col];
                    C[(size_t)row * ldc + col] = v;
                } else if (mode == 3) {
                    int b = row & 31, ti = row >> 5;
                    C[(size_t)b * (Tt * Vv) + (size_t)ti * Vv + col] = v;
                } else if (mode == 4) {
                    if (bias) v += bias[col];
                    int b = row & 31, ti = row >> 5;
                    C[((size_t)ti * Hh + col) * 32 + b] = v;
                } else { // 5
                    int b = row & 31;
                    float tv = tanhf(v);
                    C[(size_t)b * Hh + col] = tv;
                    ((float*)add1)[ptidx(col, b)] = tv;
                }
            }
        }
    }
}

// ================= persistent recurrence =================
__device__ __forceinline__ unsigned long long pack2(float2 v) {
    unsigned long long r;
    asm("mov.b64 %0, {%1, %2};" : "=l"(r) : "f"(v.x), "f"(v.y));
    return r;
}
__device__ __forceinline__ unsigned long long pack2f(float a, float b) {
    unsigned long long r;
    asm("mov.b64 %0, {%1, %2};" : "=l"(r) : "f"(a), "f"(b));
    return r;
}
__device__ __forceinline__ float2 unpack2(unsigned long long v) {
    float2 r;
    asm("mov.b64 {%0, %1}, %2;" : "=f"(r.x), "=f"(r.y) : "l"(v));
    return r;
}
__device__ __forceinline__ void ffma2(unsigned long long &acc, unsigned long long a, unsigned long long b) {
    asm("fma.rn.f32x2 %0, %1, %2, %0;" : "+l"(acc) : "l"(a), "l"(b));
}

__device__ __forceinline__ void gbar(unsigned &tgt) {
    __threadfence();
    __syncthreads();
    if (threadIdx.x == 0) {
        atomicAdd(&g_barctr, 1u);
        unsigned v;
        do {
            asm volatile("ld.acquire.gpu.global.u32 %0, [%1];" : "=r"(v) : "l"(&g_barctr) : "memory");
            if (v >= tgt) break;
            __nanosleep(16);
        } while (true);
    }
    __syncthreads();
    tgt += gridDim.x;
}

#define SMEM_RECUR (28352*4)

__global__ __launch_bounds__(256, 1)
void recur_persist(float* __restrict__ hT2, float* __restrict__ rhT2,
    const float* __restrict__ GUr, const float* __restrict__ GUz, const float* __restrict__ GUc,
    const float* __restrict__ Xr, const float* __restrict__ Xz, const float* __restrict__ Xc,
    const float* __restrict__ ctxR, const float* __restrict__ ctxZ, const float* __restrict__ ctxC,
    float* __restrict__ Sst, int nsteps)
{
    extern __shared__ float sm[];
    float* usr = sm;
    float* usz = sm + 8000;
    float* usc = sm + 16000;
    float* red = sm + 24000;
    float* zs  = sm + 28096;
    int tid = threadIdx.x, lane = tid & 31, w = tid >> 5;
    int jbase = blockIdx.x * NCOLS;

    for (int i4 = tid; i4 < 2000; i4 += 256) {
        int row = i4 / 250, k4 = (i4 % 250) * 4;
        *(float4*)(usr + row * 1000 + k4) = *(const float4*)(GUr + (size_t)(jbase + row) * 1000 + k4);
        *(float4*)(usz + row * 1000 + k4) = *(const float4*)(GUz + (size_t)(jbase + row) * 1000 + k4);
        *(float4*)(usc + row * 1000 + k4) = *(const float4*)(GUc + (size_t)(jbase + row) * 1000 + k4);
    }
    __syncthreads();

    const int offs[8] = {0, 64, 128, 192, 256, 318, 380, 440};
    const int lens[8] = {64, 64, 64, 64, 62, 62, 60, 60};
    int off = offs[w], len = lens[w];
    unsigned tgt = gridDim.x;

    for (int step = 0; step < nsteps; step++) {
        // ---------- phase A: r,z gates ----------
        {
            unsigned long long acc[16];
#pragma unroll
            for (int p = 0; p < 16; p++) acc[p] = 0ull;
            float2 h0 = *(const float2*)(hT2 + (off) * 64 + 2 * lane);
            float2 h1 = *(const float2*)(hT2 + (off + 1) * 64 + 2 * lane);
            for (int i = 0; i < len; i += 2) {
                float2 n0, n1;
                if (i + 2 < len) {
                    n0 = *(const float2*)(hT2 + (off + i + 2) * 64 + 2 * lane);
                    n1 = *(const float2*)(hT2 + (off + i + 3) * 64 + 2 * lane);
                }
                int k0 = (off + i) * 2;
                unsigned long long h0p = pack2(h0), h1p = pack2(h1);
#pragma unroll
                for (int p = 0; p < 16; p++) {
                    const float* us = (p & 1) ? usz : usr;
                    float4 u = *(const float4*)(us + (p >> 1) * 1000 + k0);
                    ffma2(acc[p], h0p, pack2f(u.x, u.y));
                    ffma2(acc[p], h1p, pack2f(u.z, u.w));
                }
                h0 = n0; h1 = n1;
            }
#pragma unroll
            for (int p = 0; p < 16; p++) {
                float2 a = unpack2(acc[p]);
                red[w * 512 + p * 32 + lane] = a.x + a.y;
            }
            __syncthreads();
            for (int o = tid; o < 512; o += 256) {
                int p = o >> 5, b = o & 31;
                int col = p >> 1, gate = p & 1;
                int jg = jbase + col;
                float s = 0.f;
#pragma unroll
                for (int ww = 0; ww < 8; ww++) s += red[ww * 512 + p * 32 + b];
                const float* X = gate ? Xz : Xr;
                float pre = X[((size_t)step * Hh + jg) * 32 + b] + s;
                const float* ctx = gate ? ctxZ : ctxR;
                if (ctx) pre += ctx[jg * 32 + b];
                float sg = 1.f / (1.f + __expf(-pre));
                if (gate == 0) {
                    int hi = ptidx(jg, b);
                    rhT2[hi] = sg * hT2[hi];
                } else {
                    zs[col * 32 + b] = sg;
                }
            }
        }
        gbar(tgt);
        // ---------- phase B: candidate + blend ----------
        {
            unsigned long long acc[8];
#pragma unroll
            for (int p = 0; p < 8; p++) acc[p] = 0ull;
            float2 h0 = *(const float2*)(rhT2 + (off) * 64 + 2 * lane);
            float2 h1 = *(const float2*)(rhT2 + (off + 1) * 64 + 2 * lane);
            for (int i = 0; i < len; i += 2) {
                float2 n0, n1;
                if (i + 2 < len) {
                    n0 = *(const float2*)(rhT2 + (off + i + 2) * 64 + 2 * lane);
                    n1 = *(const float2*)(rhT2 + (off + i + 3) * 64 + 2 * lane);
                }
                int k0 = (off + i) * 2;
                unsigned long long h0p = pack2(h0), h1p = pack2(h1);
#pragma unroll
                for (int p = 0; p < 8; p++) {
                    float4 u = *(const float4*)(usc + p * 1000 + k0);
                    ffma2(acc[p], h0p, pack2f(u.x, u.y));
                    ffma2(acc[p], h1p, pack2f(u.z, u.w));
                }
                h0 = n0; h1 = n1;
            }
            __syncthreads();
#pragma unroll
            for (int p = 0; p < 8; p++) {
                float2 a = unpack2(acc[p]);
                red[w * 256 + p * 32 + lane] = a.x + a.y;
            }
            __syncthreads();
            {
                int col = tid >> 5, b = tid & 31;
                int jg = jbase + col;
                float s = 0.f;
#pragma unroll
                for (int ww = 0; ww < 8; ww++) s += red[ww * 256 + col * 32 + b];
                float pre = Xc[((size_t)step * Hh + jg) * 32 + b] + s;
                if (ctxC) pre += ctxC[jg * 32 + b];
                float cand = tanhf(pre);
                float zv = zs[col * 32 + b];
                int hi = ptidx(jg, b);
                float hv = hT2[hi];
                float hn = (1.f - zv) * hv + zv * cand;
                hT2[hi] = hn;
                if (Sst != nullptr && step + 1 < nsteps)
                    Sst[((size_t)(step + 1) * 32 + b) * Hh + jg] = hn;
            }
        }
        gbar(tgt);
    }
}

// ---------------- maxout ----------------
__global__ void maxout_k(const float* __restrict__ tf, float* __restrict__ tm)
{
    int i = blockIdx.x * blockDim.x + threadIdx.x;
    int total = RT * Mm;
    if (i < total) {
        int r = i / Mm, m = i - r * Mm;
        tm[i] = fmaxf(tf[r * Hh + 2 * m], tf[r * Hh + 2 * m + 1]);
    }
}

// ---------------- host orchestration ----------------
extern "C" void kernel_launch(void* const* d_in, const int* in_sizes, int n_in,
                              void* d_out, int out_size)
{
    const int*   src     = (const int*)d_in[0];
    const int*   tgt     = (const int*)d_in[1];
    const float* src_emb = (const float*)d_in[3];
    const float* tgt_emb = (const float*)d_in[4];
    const float* enc_W   = (const float*)d_in[5];
    const float* enc_Wz  = (const float*)d_in[6];
    const float* enc_Wr  = (const float*)d_in[7];
    const float* enc_U   = (const float*)d_in[8];
    const float* enc_Uz  = (const float*)d_in[9];
    const float* enc_Ur  = (const float*)d_in[10];
    const float* enc_b   = (const float*)d_in[11];
    const float* enc_bz  = (const float*)d_in[12];
    const float* enc_br  = (const float*)d_in[13];
    const float* dec_W   = (const float*)d_in[14];
    const float* dec_Wz  = (const float*)d_in[15];
    const float* dec_Wr  = (const float*)d_in[16];
    const float* dec_U   = (const float*)d_in[17];
    const float* dec_Uz  = (const float*)d_in[18];
    const float* dec_Ur  = (const float*)d_in[19];
    const float* dec_C   = (const float*)d_in[20];
    const float* dec_Cz  = (const float*)d_in[21];
    const float* dec_Cr  = (const float*)d_in[22];
    const float* dec_b   = (const float*)d_in[23];
    const float* dec_bz  = (const float*)d_in[24];
    const float* dec_br  = (const float*)d_in[25];
    const float* W_s     = (const float*)d_in[26];
    const float* U_o     = (const float*)d_in[27];
    const float* V_o     = (const float*)d_in[28];
    const float* C_o     = (const float*)d_in[29];
    const float* W_o     = (const float*)d_in[30];
    float* out = (float*)d_out;

    float *Xsrc, *Ytgt, *Xr, *Xz, *Xc, *Yr, *Yz, *Yc, *Yo;
    float *hT2, *s0T, *rhT2, *cCrT, *cCzT, *cCT, *cCo, *Sst, *tfull, *tmax;
    unsigned* barctr;
    cudaGetSymbolAddress((void**)&Xsrc, g_Xsrc);
    cudaGetSymbolAddress((void**)&Ytgt, g_Ytgt);
    cudaGetSymbolAddress((void**)&Xr, g_Xr);
    cudaGetSymbolAddress((void**)&Xz, g_Xz);
    cudaGetSymbolAddress((void**)&Xc, g_Xc);
    cudaGetSymbolAddress((void**)&Yr, g_Yr);
    cudaGetSymbolAddress((void**)&Yz, g_Yz);
    cudaGetSymbolAddress((void**)&Yc, g_Yc);
    cudaGetSymbolAddress((void**)&Yo, g_Yo);
    cudaGetSymbolAddress((void**)&hT2, g_hT2);
    cudaGetSymbolAddress((void**)&s0T, g_s0T);
    cudaGetSymbolAddress((void**)&rhT2, g_rhT2);
    cudaGetSymbolAddress((void**)&cCrT, g_cCrT);
    cudaGetSymbolAddress((void**)&cCzT, g_cCzT);
    cudaGetSymbolAddress((void**)&cCT,  g_cCT);
    cudaGetSymbolAddress((void**)&cCo, g_cCo);
    cudaGetSymbolAddress((void**)&Sst, g_S);
    cudaGetSymbolAddress((void**)&tfull, g_tfull);
    cudaGetSymbolAddress((void**)&tmax, g_tmax);
    cudaGetSymbolAddress((void**)&barctr, g_barctr);

    __nv_bfloat16 *eWr3, *eWz3, *eW3, *dWr3, *dWz3, *dW3, *Vo3;
    __nv_bfloat16 *Ws3, *Cr3, *Cz3, *C3, *Co3, *Uo3, *Wo3;
    __nv_bfloat16 *X3, *Y3, *cT3, *S3, *T3;
    cudaGetSymbolAddress((void**)&eWr3, g3_eWr);
    cudaGetSymbolAddress((void**)&eWz3, g3_eWz);
    cudaGetSymbolAddress((void**)&eW3,  g3_eW);
    cudaGetSymbolAddress((void**)&dWr3, g3_dWr);
    cudaGetSymbolAddress((void**)&dWz3, g3_dWz);
    cudaGetSymbolAddress((void**)&dW3,  g3_dW);
    cudaGetSymbolAddress((void**)&Vo3,  g3_Vo);
    cudaGetSymbolAddress((void**)&Ws3,  g3_Ws);
    cudaGetSymbolAddress((void**)&Cr3,  g3_Cr);
    cudaGetSymbolAddress((void**)&Cz3,  g3_Cz);
    cudaGetSymbolAddress((void**)&C3,   g3_C);
    cudaGetSymbolAddress((void**)&Co3,  g3_Co);
    cudaGetSymbolAddress((void**)&Uo3,  g3_Uo);
    cudaGetSymbolAddress((void**)&Wo3,  g3_Wo);
    cudaGetSymbolAddress((void**)&X3,   g3_X);
    cudaGetSymbolAddress((void**)&Y3,   g3_Y);
    cudaGetSymbolAddress((void**)&cT3,  g3_cT);
    cudaGetSymbolAddress((void**)&S3,   g3_S);
    cudaGetSymbolAddress((void**)&T3,   g3_T);

    cudaFuncSetAttribute(recur_persist, cudaFuncAttributeMaxDynamicSharedMemorySize, SMEM_RECUR);
    cudaFuncSetAttribute(bf16_gemm, cudaFuncAttributeMaxDynamicSharedMemorySize, GSMEM_BYTES);

    // ---- weight converts (independent of data flow) ----
    {
        ConvBatch cb = {};
        const float* s[7] = {enc_Wr, enc_Wz, enc_W, dec_Wr, dec_Wz, dec_W, V_o};
        __nv_bfloat16* d[7] = {eWr3, eWz3, eW3, dWr3, dWz3, dW3, Vo3};
        for (int i = 0; i < 7; i++) cb.e[i] = {s[i], d[i], Hh, Ee, K3E, 1, 0};
        int total = Hh * (K3E / 8);
        dim3 gr((total + 255) / 256, 7);
        conv_k<<<gr, 256>>>(cb);
    }
    {
        ConvBatch cb = {};
        const float* s[6] = {W_s, dec_Cr, dec_Cz, dec_C, C_o, U_o};
        __nv_bfloat16* d[6] = {Ws3, Cr3, Cz3, C3, Co3, Uo3};
        for (int i = 0; i < 6; i++) cb.e[i] = {s[i], d[i], Hh, Hh, K3H, 1, 0};
        int total = Hh * (K3H / 8);
        dim3 gr((total + 255) / 256, 6);
        conv_k<<<gr, 256>>>(cb);
    }
    {
        ConvBatch cb = {};
        cb.e[0] = {W_o, Wo3, Vv, Mm, K3M, 1, 0};
        int total = Vv * (K3M / 8);
        dim3 gr((total + 255) / 256, 1);
        conv_k<<<gr, 256>>>(cb);
    }

    // ---- gathers + A converts ----
    gather_emb<<<RS, 128>>>(src, src_emb, Xsrc, Ss);
    gather_emb<<<RT, 128>>>(tgt, tgt_emb, Ytgt, Tt);
    {
        ConvBatch cb = {};
        cb.e[0] = {Xsrc, X3, RS, Ee, K3E, 0, 0};
        cb.e[1] = {Ytgt, Y3, RT, Ee, K3E, 0, 0};
        int total = RS * (K3E / 8);
        dim3 gr((total + 255) / 256, 2);
        conv_k<<<gr, 256>>>(cb);
    }

    // ---- input projections ----
    {
        MultiGemm g = {};
        g.A3 = X3; g.M = RS; g.N = Hh; g.K3p = K3E; g.ldc = Hh;
        g.B3[0] = eWr3; g.C[0] = Xr; g.bias[0] = enc_br; g.mode[0] = 4;
        g.B3[1] = eWz3; g.C[1] = Xz; g.bias[1] = enc_bz; g.mode[1] = 4;
        g.B3[2] = eW3;  g.C[2] = Xc; g.bias[2] = enc_b;  g.mode[2] = 4;
        dim3 gr((Hh + GBN - 1) / GBN, (RS + GBM - 1) / GBM, 3);
        bf16_gemm<<<gr, 256, GSMEM_BYTES>>>(g);
    }
    {
        MultiGemm g = {};
        g.A3 = Y3; g.M = RT; g.N = Hh; g.K3p = K3E; g.ldc = Hh;
        g.B3[0] = dWr3; g.C[0] = Yr; g.bias[0] = dec_br; g.mode[0] = 4;
        g.B3[1] = dWz3; g.C[1] = Yz; g.bias[1] = dec_bz; g.mode[1] = 4;
        g.B3[2] = dW3;  g.C[2] = Yc; g.bias[2] = dec_b;  g.mode[2] = 4;
        g.B3[3] = Vo3;  g.C[3] = Yo; g.bias[3] = nullptr; g.mode[3] = 0;
        dim3 gr((Hh + GBN - 1) / GBN, (RT + GBM - 1) / GBM, 4);
        bf16_gemm<<<gr, 256, GSMEM_BYTES>>>(g);
    }

    // ---- encoder recurrence ----
    cudaMemsetAsync(hT2, 0, (size_t)Hh * Bb * sizeof(float));
    cudaMemsetAsync(barctr, 0, sizeof(unsigned));
    recur_persist<<<NBLK, 256, SMEM_RECUR>>>(hT2, rhT2,
        enc_Ur, enc_Uz, enc_U, Xr, Xz, Xc,
        nullptr, nullptr, nullptr, nullptr, Ss);

    // ---- context projections (A = c, paired -> tripled) ----
    {
        ConvBatch cb = {};
        cb.e[0] = {hT2, cT3, Bb, Hh, K3H, 0, 1};
        int total = Bb * (K3H / 8);
        dim3 gr((total + 255) / 256, 1);
        conv_k<<<gr, 256>>>(cb);
    }
    {
        MultiGemm g = {};
        g.A3 = cT3; g.M = Bb; g.N = Hh; g.K3p = K3H; g.ldc = Hh;
        g.B3[0] = Ws3; g.C[0] = Sst;  g.add1[0] = s0T; g.mode[0] = 5;
        g.B3[1] = Cr3; g.C[1] = cCrT; g.mode[1] = 4;
        g.B3[2] = Cz3; g.C[2] = cCzT; g.mode[2] = 4;
        g.B3[3] = C3;  g.C[3] = cCT;  g.mode[3] = 4;
        g.B3[4] = Co3; g.C[4] = cCo;  g.mode[4] = 0;
        dim3 gr((Hh + GBN - 1) / GBN, 1, 5);
        bf16_gemm<<<gr, 256, GSMEM_BYTES>>>(g);
    }

    // ---- decoder recurrence ----
    cudaMemsetAsync(barctr, 0, sizeof(unsigned));
    recur_persist<<<NBLK, 256, SMEM_RECUR>>>(s0T, rhT2,
        dec_Ur, dec_Uz, dec_U, Yr, Yz, Yc,
        cCrT, cCzT, cCT, Sst, Tt);

    // ---- output layer ----
    {
        ConvBatch cb = {};
        cb.e[0] = {Sst, S3, RT, Hh, K3H, 0, 0};
        int total = RT * (K3H / 8);
        dim3 gr((total + 255) / 256, 1);
        conv_k<<<gr, 256>>>(cb);
    }
    {
        MultiGemm g = {};
        g.A3 = S3; g.M = RT; g.N = Hh; g.K3p = K3H; g.ldc = Hh;
        g.B3[0] = Uo3; g.C[0] = tfull; g.add1[0] = Yo; g.add2[0] = cCo; g.mode[0] = 2;
        dim3 gr((Hh + GBN - 1) / GBN, (RT + GBM - 1) / GBM, 1);
        bf16_gemm<<<gr, 256, GSMEM_BYTES>>>(g);
    }
    maxout_k<<<(RT * Mm + 255) / 256, 256>>>(tfull, tmax);
    {
        ConvBatch cb = {};
        cb.e[0] = {tmax, T3, RT, Mm, K3M, 0, 0};
        int total = RT * (K3M / 8);
        dim3 gr((total + 255) / 256, 1);
        conv_k<<<gr, 256>>>(cb);
    }
    {
        MultiGemm g = {};
        g.A3 = T3; g.M = RT; g.N = Vv; g.K3p = K3M; g.ldc = Vv;
        g.B3[0] = Wo3; g.C[0] = out; g.mode[0] = 3;
        dim3 gr((Vv + GBN - 1) / GBN, (RT + GBM - 1) / GBM, 1);
        bf16_gemm<<<gr, 256, GSMEM_BYTES>>>(g);
    }
}